// round 4
// baseline (speedup 1.0000x reference)
#include <cuda_runtime.h>

typedef unsigned long long u64;

#define IMG_H 1024
#define IMG_W 1024
#define IMG_HW (IMG_H * IMG_W)
#define WS 128
#define HALF 64
#define NE 6
#define NF 7
#define DH 16
#define NC 512
#define PX_PER_C (WS * WS)
#define PROB_ELEMS (NC * PX_PER_C)

#define THREADS 256
#define PIX 4
#define PIXB (THREADS * PIX)
#define BLOCKS_X (PX_PER_C / PIXB)

// ---- packed f32x2 helpers ----
__device__ __forceinline__ u64 pk2(float lo, float hi) {
    u64 r; asm("mov.b64 %0, {%1, %2};" : "=l"(r) : "f"(lo), "f"(hi)); return r;
}
__device__ __forceinline__ void up2(u64 v, float& a, float& b) {
    asm("mov.b64 {%0, %1}, %2;" : "=f"(a), "=f"(b) : "l"(v));
}
__device__ __forceinline__ u64 fma2(u64 a, u64 b, u64 c) {
    u64 d; asm("fma.rn.f32x2 %0, %1, %2, %3;" : "=l"(d) : "l"(a), "l"(b), "l"(c)); return d;
}
__device__ __forceinline__ u64 relu2(u64 v) {
    float a, b; up2(v, a, b);
    return pk2(fmaxf(a, 0.0f), fmaxf(b, 0.0f));
}

__global__ __launch_bounds__(THREADS, 2)
void instanseg_kernel(const float* __restrict__ x,
                      const float* __restrict__ sigma,
                      const float* __restrict__ cvec,
                      const float* __restrict__ W1,
                      const float* __restrict__ b1,
                      const float* __restrict__ W2,
                      const float* __restrict__ b2,
                      const float* __restrict__ W3,
                      const float* __restrict__ b3,
                      const int*   __restrict__ cent,
                      float* __restrict__ out,
                      int write_iidd)
{
    // Weights in NATURAL layout (no duplication): one LDS.128 = 4 neurons
    // = two f32x2 operands. Accumulators hold neuron-pairs per pixel.
    __shared__ float4 w1q[NF * DH / 4];   // 28
    __shared__ float4 w2q[DH * DH / 4];   // 64
    __shared__ float4 b1cq[DH / 4];       // b1 - c@W1[0:6]
    __shared__ float4 b2q[DH / 4];
    __shared__ float4 w3q[DH / 4];
    __shared__ float  bias3;
    __shared__ int    cy0s, cx0s;

    const int tid = threadIdx.x;
    const int cid = blockIdx.y;

    if (tid < DH * DH / 4) w2q[tid] = ((const float4*)W2)[tid];
    if (tid < NF * DH / 4) w1q[tid] = ((const float4*)W1)[tid];
    if (tid < DH) {
        ((float*)b2q)[tid] = b2[tid];
        ((float*)w3q)[tid] = W3[tid];
        float acc = b1[tid];
        #pragma unroll
        for (int e = 0; e < NE; e++)
            acc -= cvec[cid * NE + e] * W1[e * DH + tid];
        ((float*)b1cq)[tid] = acc;
    }
    if (tid == 0) {
        bias3 = b3[0];
        int cy = cent[cid * 2 + 0];
        int cx = cent[cid * 2 + 1];
        cy = min(max(cy, HALF), IMG_H - HALF);
        cx = min(max(cx, HALF), IMG_W - HALF);
        cy0s = cy - HALF;
        cx0s = cx - HALF;
    }
    __syncthreads();

    const int cy0 = cy0s, cx0 = cx0s;
    const int base = blockIdx.x * PIXB;

    const ulonglong2* w1u  = (const ulonglong2*)w1q;
    const ulonglong2* w2u  = (const ulonglong2*)w2q;
    const ulonglong2* b1cu = (const ulonglong2*)b1cq;
    const ulonglong2* b2u  = (const ulonglong2*)b2q;
    const ulonglong2* w3u  = (const ulonglong2*)w3q;

    // ---- pixel offsets ----
    int off[PIX];
    #pragma unroll
    for (int i = 0; i < PIX; i++) {
        int p = base + i * THREADS + tid;
        off[i] = (cy0 + (p >> 7)) * IMG_W + (cx0 + (p & (WS - 1)));
    }

    // ---- layer 1: 7 -> 16; h1p[i][kk] = (h1[2kk], h1[2kk+1]) ----
    u64 h1p[PIX][8];
    #pragma unroll
    for (int q = 0; q < 4; q++) {
        ulonglong2 b = b1cu[q];
        #pragma unroll
        for (int i = 0; i < PIX; i++) {
            h1p[i][2*q]   = b.x;
            h1p[i][2*q+1] = b.y;
        }
    }
    #pragma unroll
    for (int k = 0; k < NF; k++) {
        const float* xk = (k < NE) ? (x + k * IMG_HW) : sigma;
        u64 vd[PIX];
        #pragma unroll
        for (int i = 0; i < PIX; i++) {
            float v = xk[off[i]];
            vd[i] = pk2(v, v);
        }
        #pragma unroll
        for (int q = 0; q < 4; q++) {
            ulonglong2 w = w1u[k * 4 + q];
            #pragma unroll
            for (int i = 0; i < PIX; i++) {
                h1p[i][2*q]   = fma2(vd[i], w.x, h1p[i][2*q]);
                h1p[i][2*q+1] = fma2(vd[i], w.y, h1p[i][2*q+1]);
            }
        }
    }
    // relu in place
    #pragma unroll
    for (int i = 0; i < PIX; i++)
        #pragma unroll
        for (int kk = 0; kk < 8; kk++)
            h1p[i][kk] = relu2(h1p[i][kk]);

    // ---- layer 2 (j-chunked, 8 neurons/chunk) + fused relu + layer 3 ----
    u64 zp[PIX];
    #pragma unroll
    for (int i = 0; i < PIX; i++) zp[i] = pk2(bias3, 0.0f);

    #pragma unroll
    for (int c = 0; c < 2; c++) {
        u64 h2[PIX][4];   // neuron pairs (8c,8c+1)..(8c+6,8c+7)
        {
            ulonglong2 b0 = b2u[c * 2], b1v = b2u[c * 2 + 1];
            #pragma unroll
            for (int i = 0; i < PIX; i++) {
                h2[i][0] = b0.x; h2[i][1] = b0.y;
                h2[i][2] = b1v.x; h2[i][3] = b1v.y;
            }
        }
        #pragma unroll
        for (int kk = 0; kk < 8; kk++) {
            u64 da[PIX], db[PIX];
            #pragma unroll
            for (int i = 0; i < PIX; i++) {
                float a, b;
                up2(h1p[i][kk], a, b);
                da[i] = pk2(a, a);
                db[i] = pk2(b, b);
            }
            ulonglong2 wA0 = w2u[(2*kk)   * 4 + c*2];
            ulonglong2 wA1 = w2u[(2*kk)   * 4 + c*2 + 1];
            ulonglong2 wB0 = w2u[(2*kk+1) * 4 + c*2];
            ulonglong2 wB1 = w2u[(2*kk+1) * 4 + c*2 + 1];
            #pragma unroll
            for (int i = 0; i < PIX; i++) {
                h2[i][0] = fma2(da[i], wA0.x, h2[i][0]);
                h2[i][1] = fma2(da[i], wA0.y, h2[i][1]);
                h2[i][2] = fma2(da[i], wA1.x, h2[i][2]);
                h2[i][3] = fma2(da[i], wA1.y, h2[i][3]);
                h2[i][0] = fma2(db[i], wB0.x, h2[i][0]);
                h2[i][1] = fma2(db[i], wB0.y, h2[i][1]);
                h2[i][2] = fma2(db[i], wB1.x, h2[i][2]);
                h2[i][3] = fma2(db[i], wB1.y, h2[i][3]);
            }
        }
        // layer 3 partial accumulation (packed)
        ulonglong2 w30 = w3u[c * 2], w31 = w3u[c * 2 + 1];
        #pragma unroll
        for (int i = 0; i < PIX; i++) {
            zp[i] = fma2(relu2(h2[i][0]), w30.x, zp[i]);
            zp[i] = fma2(relu2(h2[i][1]), w30.y, zp[i]);
            zp[i] = fma2(relu2(h2[i][2]), w31.x, zp[i]);
            zp[i] = fma2(relu2(h2[i][3]), w31.y, zp[i]);
        }
    }

    // ---- sigmoid + stores ----
    #pragma unroll
    for (int i = 0; i < PIX; i++) {
        float zl, zh;
        up2(zp[i], zl, zh);
        float z = zl + zh;
        float p = __fdividef(1.0f, 1.0f + __expf(-z));

        int pidx = base + i * THREADS + tid;
        int gy = pidx >> 7;
        int gx = pidx & (WS - 1);
        long gidx = (long)cid * PX_PER_C + pidx;
        out[gidx] = p;
        if (write_iidd) {
            out[(long)PROB_ELEMS     + gidx] = (float)cid;
            out[(long)2 * PROB_ELEMS + gidx] = (float)(cy0 + gy);
            out[(long)3 * PROB_ELEMS + gidx] = (float)(cx0 + gx);
        }
    }
}

extern "C" void kernel_launch(void* const* d_in, const int* in_sizes, int n_in,
                              void* d_out, int out_size)
{
    const float* x     = (const float*)d_in[0];
    const float* sigma = (const float*)d_in[1];
    const float* cvec  = (const float*)d_in[2];
    const float* W1    = (const float*)d_in[3];
    const float* b1    = (const float*)d_in[4];
    const float* W2    = (const float*)d_in[5];
    const float* b2    = (const float*)d_in[6];
    const float* W3    = (const float*)d_in[7];
    const float* b3    = (const float*)d_in[8];
    const int*   cent  = (const int*)d_in[9];
    float* out = (float*)d_out;

    int write_iidd = (out_size >= 4 * PROB_ELEMS) ? 1 : 0;

    dim3 grid(BLOCKS_X, NC);
    instanseg_kernel<<<grid, THREADS>>>(x, sigma, cvec, W1, b1, W2, b2, W3, b3,
                                        cent, out, write_iidd);
}

// round 5
// speedup vs baseline: 1.5361x; 1.5361x over previous
#include <cuda_runtime.h>

#define IMG_H 1024
#define IMG_W 1024
#define IMG_HW (IMG_H * IMG_W)
#define WS 128
#define HALF 64
#define NE 6
#define NF 7
#define DH 16
#define NC 512
#define PX_PER_C (WS * WS)
#define PROB_ELEMS (NC * PX_PER_C)

#define THREADS 256          // 8 warps
#define WARPS 8
#define TILE_PX 16           // one m16n8k8 m-tile = 16 pixels
#define TILES_PER_WARP 8     // warp covers 128 px; CTA covers 1024 px
#define BLOCKS_X 16          // 16 * 1024 = 16384 px per centroid

#define H1_STRIDE 20         // padded row stride (floats) -> conflict-free A-frag loads

__device__ __forceinline__ unsigned f2tf32(float f) {
    unsigned r; asm("cvt.rna.tf32.f32 %0, %1;" : "=r"(r) : "f"(f)); return r;
}

// d += a * b   (m16n8k8, tf32 in, f32 accumulate)
__device__ __forceinline__ void mma8(float& d0, float& d1, float& d2, float& d3,
                                     unsigned a0, unsigned a1, unsigned a2, unsigned a3,
                                     unsigned b0, unsigned b1) {
    asm volatile(
        "mma.sync.aligned.m16n8k8.row.col.f32.tf32.tf32.f32 "
        "{%0,%1,%2,%3}, {%4,%5,%6,%7}, {%8,%9}, {%0,%1,%2,%3};"
        : "+f"(d0), "+f"(d1), "+f"(d2), "+f"(d3)
        : "r"(a0), "r"(a1), "r"(a2), "r"(a3), "r"(b0), "r"(b1));
}

__global__ __launch_bounds__(THREADS, 2)
void instanseg_kernel(const float* __restrict__ x,
                      const float* __restrict__ sigma,
                      const float* __restrict__ cvec,
                      const float* __restrict__ W1,
                      const float* __restrict__ b1,
                      const float* __restrict__ W2,
                      const float* __restrict__ b2,
                      const float* __restrict__ W3,
                      const float* __restrict__ b3,
                      const int*   __restrict__ cent,
                      float* __restrict__ out,
                      int write_iidd)
{
    __shared__ float b1cs[DH];                     // b1 - c[cid] @ W1[0:6]
    __shared__ float h1s[WARPS][TILE_PX * H1_STRIDE];  // per-warp staging (tf32 bits)
    __shared__ int   cy0s, cx0s;

    const int tid  = threadIdx.x;
    const int wid  = tid >> 5;
    const int lane = tid & 31;
    const int g_   = lane >> 2;    // group id (row base)
    const int c_   = lane & 3;     // thread-in-group (col base)
    const int cid  = blockIdx.y;

    // ---- per-block setup ----
    if (tid < DH) {
        float acc = b1[tid];
        #pragma unroll
        for (int e = 0; e < NE; e++)
            acc -= cvec[cid * NE + e] * W1[e * DH + tid];
        b1cs[tid] = acc;
    }
    if (tid == 0) {
        int cy = cent[cid * 2 + 0];
        int cx = cent[cid * 2 + 1];
        cy = min(max(cy, HALF), IMG_H - HALF);
        cx = min(max(cx, HALF), IMG_W - HALF);
        cy0s = cy - HALF;
        cx0s = cx - HALF;
    }
    __syncthreads();

    const int cy0 = cy0s, cx0 = cx0s;

    // ---- persistent per-thread fragments (loaded once) ----
    // W1 B-fragments, hi/lo split.  B[k][n]: b0 k=c_, b1 k=c_+4; n = t*8 + g_.
    unsigned w1hi[2][2], w1lo[2][2];
    #pragma unroll
    for (int t = 0; t < 2; t++) {
        int n = t * 8 + g_;
        float wb0 = W1[c_ * DH + n];
        float wb1 = (c_ + 4 < NF) ? W1[(c_ + 4) * DH + n] : 0.0f;
        w1hi[t][0] = f2tf32(wb0);
        w1lo[t][0] = f2tf32(wb0 - __uint_as_float(w1hi[t][0]));
        w1hi[t][1] = f2tf32(wb1);
        w1lo[t][1] = f2tf32(wb1 - __uint_as_float(w1hi[t][1]));
    }
    // W2 B-fragments per k-step s, n-tile t.
    unsigned w2hi[2][2][2], w2lo[2][2][2];
    #pragma unroll
    for (int s = 0; s < 2; s++)
        #pragma unroll
        for (int t = 0; t < 2; t++) {
            int n = t * 8 + g_;
            float wb0 = W2[(s * 8 + c_)     * DH + n];
            float wb1 = W2[(s * 8 + c_ + 4) * DH + n];
            w2hi[s][t][0] = f2tf32(wb0);
            w2lo[s][t][0] = f2tf32(wb0 - __uint_as_float(w2hi[s][t][0]));
            w2hi[s][t][1] = f2tf32(wb1);
            w2lo[s][t][1] = f2tf32(wb1 - __uint_as_float(w2hi[s][t][1]));
        }
    // biases / layer-3 weights for the 4 output cols this thread owns (cols t*8+2c_, +1)
    float bias1[2][2], bias2[2][2], w3r[2][2];
    #pragma unroll
    for (int t = 0; t < 2; t++) {
        int col = t * 8 + 2 * c_;
        bias1[t][0] = b1cs[col];     bias1[t][1] = b1cs[col + 1];
        bias2[t][0] = b2[col];       bias2[t][1] = b2[col + 1];
        w3r[t][0]   = W3[col];       w3r[t][1]   = W3[col + 1];
    }
    const float b3v = b3[0];

    // gather plane pointers for this thread's A-fragment columns
    const float* pA = x + c_ * IMG_HW;                       // feature c_ (0..3)
    const float* pB = (c_ < 2) ? (x + (c_ + 4) * IMG_HW)
                               : ((c_ == 2) ? sigma : 0);    // feature c_+4 (4,5,6=sigma,7=pad)

    float* h1w = h1s[wid];
    const int warp_base = blockIdx.x * (BLOCKS_X * 64) + wid * (TILES_PER_WARP * TILE_PX);
    // (blockIdx.x * 1024)
    const long out_base = (long)cid * PX_PER_C;

    for (int it = 0; it < TILES_PER_WARP; it++) {
        const int tb = warp_base + it * TILE_PX;

        // ---- layer 1 A-fragment gather (pixels tb+g_, tb+g_+8) ----
        int p0 = tb + g_;
        int p1 = p0 + 8;
        int off0 = (cy0 + (p0 >> 7)) * IMG_W + (cx0 + (p0 & (WS - 1)));
        int off1 = (cy0 + (p1 >> 7)) * IMG_W + (cx0 + (p1 & (WS - 1)));
        unsigned a0 = f2tf32(pA[off0]);
        unsigned a1 = f2tf32(pA[off1]);
        unsigned a2 = pB ? f2tf32(pB[off0]) : 0u;
        unsigned a3 = pB ? f2tf32(pB[off1]) : 0u;

        // ---- layer 1: 2 n-tiles x (hi+lo) MMAs ----
        float d1[2][4];
        #pragma unroll
        for (int t = 0; t < 2; t++) {
            d1[t][0] = bias1[t][0]; d1[t][1] = bias1[t][1];
            d1[t][2] = bias1[t][0]; d1[t][3] = bias1[t][1];
            mma8(d1[t][0], d1[t][1], d1[t][2], d1[t][3], a0, a1, a2, a3, w1hi[t][0], w1hi[t][1]);
            mma8(d1[t][0], d1[t][1], d1[t][2], d1[t][3], a0, a1, a2, a3, w1lo[t][0], w1lo[t][1]);
        }

        // ---- relu + tf32 cvt + stage to smem (C layout -> memory) ----
        __syncwarp();
        #pragma unroll
        for (int t = 0; t < 2; t++) {
            int colb = t * 8 + 2 * c_;
            unsigned v0 = f2tf32(fmaxf(d1[t][0], 0.0f));
            unsigned v1 = f2tf32(fmaxf(d1[t][1], 0.0f));
            unsigned v2 = f2tf32(fmaxf(d1[t][2], 0.0f));
            unsigned v3 = f2tf32(fmaxf(d1[t][3], 0.0f));
            ((unsigned*)h1w)[g_ * H1_STRIDE + colb]           = v0;
            ((unsigned*)h1w)[g_ * H1_STRIDE + colb + 1]       = v1;
            ((unsigned*)h1w)[(g_ + 8) * H1_STRIDE + colb]     = v2;
            ((unsigned*)h1w)[(g_ + 8) * H1_STRIDE + colb + 1] = v3;
        }
        __syncwarp();

        // ---- layer 2 A-fragments from smem ----
        unsigned A2[2][4];
        #pragma unroll
        for (int s = 0; s < 2; s++) {
            int cb = s * 8 + c_;
            A2[s][0] = ((unsigned*)h1w)[g_ * H1_STRIDE + cb];
            A2[s][1] = ((unsigned*)h1w)[(g_ + 8) * H1_STRIDE + cb];
            A2[s][2] = ((unsigned*)h1w)[g_ * H1_STRIDE + cb + 4];
            A2[s][3] = ((unsigned*)h1w)[(g_ + 8) * H1_STRIDE + cb + 4];
        }

        // ---- layer 2: 2 n-tiles x 2 k-steps x (hi+lo) ----
        float d2[2][4];
        #pragma unroll
        for (int t = 0; t < 2; t++) {
            d2[t][0] = bias2[t][0]; d2[t][1] = bias2[t][1];
            d2[t][2] = bias2[t][0]; d2[t][3] = bias2[t][1];
            #pragma unroll
            for (int s = 0; s < 2; s++) {
                mma8(d2[t][0], d2[t][1], d2[t][2], d2[t][3],
                     A2[s][0], A2[s][1], A2[s][2], A2[s][3],
                     w2hi[s][t][0], w2hi[s][t][1]);
                mma8(d2[t][0], d2[t][1], d2[t][2], d2[t][3],
                     A2[s][0], A2[s][1], A2[s][2], A2[s][3],
                     w2lo[s][t][0], w2lo[s][t][1]);
            }
        }

        // ---- layer 3: per-pixel dot over this thread's 4 cols, butterfly reduce ----
        float zg = 0.0f, z8 = 0.0f;
        #pragma unroll
        for (int t = 0; t < 2; t++) {
            zg = fmaf(fmaxf(d2[t][0], 0.0f), w3r[t][0], zg);
            zg = fmaf(fmaxf(d2[t][1], 0.0f), w3r[t][1], zg);
            z8 = fmaf(fmaxf(d2[t][2], 0.0f), w3r[t][0], z8);
            z8 = fmaf(fmaxf(d2[t][3], 0.0f), w3r[t][1], z8);
        }
        zg += __shfl_xor_sync(0xffffffffu, zg, 1);
        zg += __shfl_xor_sync(0xffffffffu, zg, 2);
        z8 += __shfl_xor_sync(0xffffffffu, z8, 1);
        z8 += __shfl_xor_sync(0xffffffffu, z8, 2);

        // ---- sigmoid + stores (lanes c_==0 write row g_, c_==1 write row g_+8) ----
        if (c_ < 2) {
            float z = (c_ == 0) ? (zg + b3v) : (z8 + b3v);
            float p = __fdividef(1.0f, 1.0f + __expf(-z));
            int px = tb + g_ + c_ * 8;
            int gy = px >> 7;
            int gx = px & (WS - 1);
            long gi = out_base + px;
            out[gi] = p;
            if (write_iidd) {
                out[(long)PROB_ELEMS     + gi] = (float)cid;
                out[(long)2 * PROB_ELEMS + gi] = (float)(cy0 + gy);
                out[(long)3 * PROB_ELEMS + gi] = (float)(cx0 + gx);
            }
        }
    }
}

extern "C" void kernel_launch(void* const* d_in, const int* in_sizes, int n_in,
                              void* d_out, int out_size)
{
    const float* x     = (const float*)d_in[0];
    const float* sigma = (const float*)d_in[1];
    const float* cvec  = (const float*)d_in[2];
    const float* W1    = (const float*)d_in[3];
    const float* b1    = (const float*)d_in[4];
    const float* W2    = (const float*)d_in[5];
    const float* b2    = (const float*)d_in[6];
    const float* W3    = (const float*)d_in[7];
    const float* b3    = (const float*)d_in[8];
    const int*   cent  = (const int*)d_in[9];
    float* out = (float*)d_out;

    int write_iidd = (out_size >= 4 * PROB_ELEMS) ? 1 : 0;

    dim3 grid(BLOCKS_X, NC);
    instanseg_kernel<<<grid, THREADS>>>(x, sigma, cvec, W1, b1, W2, b2, W3, b3,
                                        cent, out, write_iidd);
}

// round 6
// speedup vs baseline: 2.1006x; 1.3675x over previous
#include <cuda_runtime.h>

#define IMG_H 1024
#define IMG_W 1024
#define IMG_HW (IMG_H * IMG_W)
#define WS 128
#define HALF 64
#define NE 6
#define NF 7
#define DH 16
#define NC 512
#define PX_PER_C (WS * WS)
#define PROB_ELEMS (NC * PX_PER_C)

#define THREADS 256          // 8 warps
#define WARPS 8
#define TILE_PX 16
#define TILES_PER_WARP 8     // warp covers one 128-px window row
#define BLOCKS_X 16

__device__ __forceinline__ unsigned f2tf32(float f) {
    unsigned r; asm("cvt.rna.tf32.f32 %0, %1;" : "=r"(r) : "f"(f)); return r;
}

// d += a * b   (m16n8k8, tf32 in, f32 accumulate)
__device__ __forceinline__ void mma8(float& d0, float& d1, float& d2, float& d3,
                                     unsigned a0, unsigned a1, unsigned a2, unsigned a3,
                                     unsigned b0, unsigned b1) {
    asm volatile(
        "mma.sync.aligned.m16n8k8.row.col.f32.tf32.tf32.f32 "
        "{%0,%1,%2,%3}, {%4,%5,%6,%7}, {%8,%9}, {%0,%1,%2,%3};"
        : "+f"(d0), "+f"(d1), "+f"(d2), "+f"(d3)
        : "r"(a0), "r"(a1), "r"(a2), "r"(a3), "r"(b0), "r"(b1));
}

__global__ __launch_bounds__(THREADS, 3)
void instanseg_kernel(const float* __restrict__ x,
                      const float* __restrict__ sigma,
                      const float* __restrict__ cvec,
                      const float* __restrict__ W1,
                      const float* __restrict__ b1,
                      const float* __restrict__ W2,
                      const float* __restrict__ b2,
                      const float* __restrict__ W3,
                      const float* __restrict__ b3,
                      const int*   __restrict__ cent,
                      float* __restrict__ out,
                      int write_iidd)
{
    __shared__ float b1cs[DH];     // b1 - c[cid] @ W1[0:6]
    __shared__ int   cy0s, cx0s;

    const int tid  = threadIdx.x;
    const int wid  = tid >> 5;
    const int lane = tid & 31;
    const int g_   = lane >> 2;
    const int c_   = lane & 3;
    const int cid  = blockIdx.y;

    if (tid < DH) {
        float acc = b1[tid];
        #pragma unroll
        for (int e = 0; e < NE; e++)
            acc -= cvec[cid * NE + e] * W1[e * DH + tid];
        b1cs[tid] = acc;
    }
    if (tid == 0) {
        int cy = cent[cid * 2 + 0];
        int cx = cent[cid * 2 + 1];
        cy = min(max(cy, HALF), IMG_H - HALF);
        cx = min(max(cx, HALF), IMG_W - HALF);
        cy0s = cy - HALF;
        cx0s = cx - HALF;
    }
    __syncthreads();

    const int cy0 = cy0s, cx0 = cx0s;

    // ---- W1 B-fragments with sigma-permuted output columns ----
    // Frag column g_ of n-tile t holds neuron nu = (g_>>1) + 8t + 4*(g_&1).
    // Result: d1[s][p] (rows g_/g_+8) holds neuron c_+8s+4p == exactly the
    // layer-2 A-fragment layout. No staging, no transpose.
    unsigned w1hi[2][2], w1lo[2][2];
    #pragma unroll
    for (int t = 0; t < 2; t++) {
        int n = (g_ >> 1) + 8 * t + 4 * (g_ & 1);
        float wb0 = W1[c_ * DH + n];
        float wb1 = (c_ + 4 < NF) ? W1[(c_ + 4) * DH + n] : 0.0f;
        w1hi[t][0] = f2tf32(wb0);
        w1lo[t][0] = f2tf32(wb0 - __uint_as_float(w1hi[t][0]));
        w1hi[t][1] = f2tf32(wb1);
        w1lo[t][1] = f2tf32(wb1 - __uint_as_float(w1hi[t][1]));
    }
    // W2 B-fragments: k-rows natural (match A neuron order), out cols natural.
    unsigned w2hi[2][2][2], w2lo[2][2][2];
    #pragma unroll
    for (int s = 0; s < 2; s++)
        #pragma unroll
        for (int t = 0; t < 2; t++) {
            int n = t * 8 + g_;
            float wb0 = W2[(s * 8 + c_)     * DH + n];
            float wb1 = W2[(s * 8 + c_ + 4) * DH + n];
            w2hi[s][t][0] = f2tf32(wb0);
            w2lo[s][t][0] = f2tf32(wb0 - __uint_as_float(w2hi[s][t][0]));
            w2hi[s][t][1] = f2tf32(wb1);
            w2lo[s][t][1] = f2tf32(wb1 - __uint_as_float(w2hi[s][t][1]));
        }
    // Layer-1 bias, permuted to match d1 layout: d1[s][p] = neuron c_+8s+4p.
    float bias1[2][2];
    #pragma unroll
    for (int s = 0; s < 2; s++) {
        bias1[s][0] = b1cs[c_ + 8 * s];
        bias1[s][1] = b1cs[c_ + 8 * s + 4];
    }
    // Layer-2 bias / layer-3 weights for natural C layout (cols t*8+2c_, +1).
    float bias2[2][2], w3r[2][2];
    #pragma unroll
    for (int t = 0; t < 2; t++) {
        int col = t * 8 + 2 * c_;
        bias2[t][0] = b2[col];  bias2[t][1] = b2[col + 1];
        w3r[t][0]   = W3[col];  w3r[t][1]   = W3[col + 1];
    }
    const float b3v = b3[0];

    // ---- hoisted addressing: each warp owns one window row ----
    const int gy  = blockIdx.x * 8 + wid;              // window row 0..127
    const int row = cy0 + gy;
    const float* pA = x + c_ * IMG_HW + row * IMG_W + cx0 + g_;
    const float* pB = ((c_ < 2) ? (x + (c_ + 4) * IMG_HW) : sigma)
                      + row * IMG_W + cx0 + g_;        // c_==3 -> b1 weight is 0

    const long rowbase = (long)cid * PX_PER_C + gy * WS + g_ + c_ * 8;
    float* o0 = out + rowbase;
    float* o1 = out + PROB_ELEMS     + rowbase;
    float* o2 = out + 2L * PROB_ELEMS + rowbase;
    float* o3 = out + 3L * PROB_ELEMS + rowbase;
    const float fcid = (float)cid;
    const float frow = (float)row;
    const float fcolbase = (float)(cx0 + g_ + c_ * 8);

    #pragma unroll
    for (int it = 0; it < TILES_PER_WARP; it++) {
        const int o = it * TILE_PX;

        // ---- gather (rows g_, g_+8 of this tile) ----
        unsigned a0 = f2tf32(pA[o]);
        unsigned a1 = f2tf32(pA[o + 8]);
        unsigned a2 = f2tf32(pB[o]);
        unsigned a3 = f2tf32(pB[o + 8]);

        // ---- layer 1: 2 permuted n-tiles x (hi+lo) ----
        float d1[2][4];
        #pragma unroll
        for (int s = 0; s < 2; s++) {
            d1[s][0] = bias1[s][0]; d1[s][1] = bias1[s][1];
            d1[s][2] = bias1[s][0]; d1[s][3] = bias1[s][1];
            mma8(d1[s][0], d1[s][1], d1[s][2], d1[s][3], a0, a1, a2, a3, w1hi[s][0], w1hi[s][1]);
            mma8(d1[s][0], d1[s][1], d1[s][2], d1[s][3], a0, a1, a2, a3, w1lo[s][0], w1lo[s][1]);
        }

        // ---- relu; registers ARE the layer-2 A-fragments (HW tf32-truncates) ----
        unsigned A2[2][4];
        #pragma unroll
        for (int s = 0; s < 2; s++) {
            A2[s][0] = __float_as_uint(fmaxf(d1[s][0], 0.0f));  // row g_,   k c_
            A2[s][1] = __float_as_uint(fmaxf(d1[s][2], 0.0f));  // row g_+8, k c_
            A2[s][2] = __float_as_uint(fmaxf(d1[s][1], 0.0f));  // row g_,   k c_+4
            A2[s][3] = __float_as_uint(fmaxf(d1[s][3], 0.0f));  // row g_+8, k c_+4
        }

        // ---- layer 2: 2 n-tiles x 2 k-steps x (hi+lo) ----
        float d2[2][4];
        #pragma unroll
        for (int t = 0; t < 2; t++) {
            d2[t][0] = bias2[t][0]; d2[t][1] = bias2[t][1];
            d2[t][2] = bias2[t][0]; d2[t][3] = bias2[t][1];
            #pragma unroll
            for (int s = 0; s < 2; s++) {
                mma8(d2[t][0], d2[t][1], d2[t][2], d2[t][3],
                     A2[s][0], A2[s][1], A2[s][2], A2[s][3],
                     w2hi[s][t][0], w2hi[s][t][1]);
                mma8(d2[t][0], d2[t][1], d2[t][2], d2[t][3],
                     A2[s][0], A2[s][1], A2[s][2], A2[s][3],
                     w2lo[s][t][0], w2lo[s][t][1]);
            }
        }

        // ---- layer 3 + butterfly reduce over the quad ----
        float zg = 0.0f, z8 = 0.0f;
        #pragma unroll
        for (int t = 0; t < 2; t++) {
            zg = fmaf(fmaxf(d2[t][0], 0.0f), w3r[t][0], zg);
            zg = fmaf(fmaxf(d2[t][1], 0.0f), w3r[t][1], zg);
            z8 = fmaf(fmaxf(d2[t][2], 0.0f), w3r[t][0], z8);
            z8 = fmaf(fmaxf(d2[t][3], 0.0f), w3r[t][1], z8);
        }
        zg += __shfl_xor_sync(0xffffffffu, zg, 1);
        zg += __shfl_xor_sync(0xffffffffu, zg, 2);
        z8 += __shfl_xor_sync(0xffffffffu, z8, 1);
        z8 += __shfl_xor_sync(0xffffffffu, z8, 2);

        // ---- sigmoid + stores (c_==0 -> row g_, c_==1 -> row g_+8) ----
        if (c_ < 2) {
            float z = ((c_ == 0) ? zg : z8) + b3v;
            float p = __fdividef(1.0f, 1.0f + __expf(-z));
            o0[o] = p;
            if (write_iidd) {
                o1[o] = fcid;
                o2[o] = frow;
                o3[o] = fcolbase + (float)o;
            }
        }
    }
}

extern "C" void kernel_launch(void* const* d_in, const int* in_sizes, int n_in,
                              void* d_out, int out_size)
{
    const float* x     = (const float*)d_in[0];
    const float* sigma = (const float*)d_in[1];
    const float* cvec  = (const float*)d_in[2];
    const float* W1    = (const float*)d_in[3];
    const float* b1    = (const float*)d_in[4];
    const float* W2    = (const float*)d_in[5];
    const float* b2    = (const float*)d_in[6];
    const float* W3    = (const float*)d_in[7];
    const float* b3    = (const float*)d_in[8];
    const int*   cent  = (const int*)d_in[9];
    float* out = (float*)d_out;

    int write_iidd = (out_size >= 4 * PROB_ELEMS) ? 1 : 0;

    dim3 grid(BLOCKS_X, NC);
    instanseg_kernel<<<grid, THREADS>>>(x, sigma, cvec, W1, b1, W2, b2, W3, b3,
                                        cent, out, write_iidd);
}

// round 7
// speedup vs baseline: 2.3008x; 1.0953x over previous
#include <cuda_runtime.h>

#define IMG_H 1024
#define IMG_W 1024
#define IMG_HW (IMG_H * IMG_W)
#define WS 128
#define HALF 64
#define NE 6
#define NF 7
#define DH 16
#define NC 512
#define PX_PER_C (WS * WS)
#define PROB_ELEMS (NC * PX_PER_C)

#define THREADS 256          // 8 warps
#define TILE_PX 16
#define TILES_PER_WARP 8     // warp covers one 128-px window row
#define BLOCKS_X 16

__device__ __forceinline__ unsigned f2tf32(float f) {
    unsigned r; asm("cvt.rna.tf32.f32 %0, %1;" : "=r"(r) : "f"(f)); return r;
}

// d += a*b (in-place accumulate)
__device__ __forceinline__ void mma8(float& d0, float& d1, float& d2, float& d3,
                                     unsigned a0, unsigned a1, unsigned a2, unsigned a3,
                                     unsigned b0, unsigned b1) {
    asm volatile(
        "mma.sync.aligned.m16n8k8.row.col.f32.tf32.tf32.f32 "
        "{%0,%1,%2,%3}, {%4,%5,%6,%7}, {%8,%9}, {%0,%1,%2,%3};"
        : "+f"(d0), "+f"(d1), "+f"(d2), "+f"(d3)
        : "r"(a0), "r"(a1), "r"(a2), "r"(a3), "r"(b0), "r"(b1));
}

// d = a*b + c, with DISTINCT C operand (bias registers) — no init MOVs
__device__ __forceinline__ void mma8_c(float& d0, float& d1, float& d2, float& d3,
                                       unsigned a0, unsigned a1, unsigned a2, unsigned a3,
                                       unsigned b0, unsigned b1,
                                       float c0, float c1, float c2, float c3) {
    asm volatile(
        "mma.sync.aligned.m16n8k8.row.col.f32.tf32.tf32.f32 "
        "{%0,%1,%2,%3}, {%4,%5,%6,%7}, {%8,%9}, {%10,%11,%12,%13};"
        : "=f"(d0), "=f"(d1), "=f"(d2), "=f"(d3)
        : "r"(a0), "r"(a1), "r"(a2), "r"(a3), "r"(b0), "r"(b1),
          "f"(c0), "f"(c1), "f"(c2), "f"(c3));
}

__global__ __launch_bounds__(THREADS, 3)
void instanseg_kernel(const float* __restrict__ x,
                      const float* __restrict__ sigma,
                      const float* __restrict__ cvec,
                      const float* __restrict__ W1,
                      const float* __restrict__ b1,
                      const float* __restrict__ W2,
                      const float* __restrict__ b2,
                      const float* __restrict__ W3,
                      const float* __restrict__ b3,
                      const int*   __restrict__ cent,
                      float* __restrict__ out,
                      int write_iidd)
{
    __shared__ float b1cs[DH];     // b1 - c[cid] @ W1[0:6]
    __shared__ int   cy0s, cx0s;

    const int tid  = threadIdx.x;
    const int wid  = tid >> 5;
    const int lane = tid & 31;
    const int g_   = lane >> 2;
    const int c_   = lane & 3;
    const int cid  = blockIdx.y;

    if (tid < DH) {
        float acc = b1[tid];
        #pragma unroll
        for (int e = 0; e < NE; e++)
            acc -= cvec[cid * NE + e] * W1[e * DH + tid];
        b1cs[tid] = acc;
    }
    if (tid == 0) {
        int cy = cent[cid * 2 + 0];
        int cx = cent[cid * 2 + 1];
        cy = min(max(cy, HALF), IMG_H - HALF);
        cx = min(max(cx, HALF), IMG_W - HALF);
        cy0s = cy - HALF;
        cx0s = cx - HALF;
    }
    __syncthreads();

    const int cy0 = cy0s, cx0 = cx0s;

    // ---- W1 B-fragments, output-permuted (sigma from R6), hi/lo exact ----
    // d1[s][p] (rows g_/g_+8) = neuron c_+8s+4p == layer-2 A-fragment layout.
    unsigned w1hi[2][2], w1lo[2][2];
    #pragma unroll
    for (int t = 0; t < 2; t++) {
        int n = (g_ >> 1) + 8 * t + 4 * (g_ & 1);
        float wb0 = W1[c_ * DH + n];
        float wb1 = (c_ + 4 < NF) ? W1[(c_ + 4) * DH + n] : 0.0f;
        w1hi[t][0] = f2tf32(wb0);
        w1lo[t][0] = f2tf32(wb0 - __uint_as_float(w1hi[t][0]));
        w1hi[t][1] = f2tf32(wb1);
        w1lo[t][1] = f2tf32(wb1 - __uint_as_float(w1hi[t][1]));
    }
    // W2 B-fragments: single rna-rounded tf32 (lo-pass dropped).
    unsigned w2r[2][2][2];
    #pragma unroll
    for (int s = 0; s < 2; s++)
        #pragma unroll
        for (int t = 0; t < 2; t++) {
            int n = t * 8 + g_;
            w2r[s][t][0] = f2tf32(W2[(s * 8 + c_)     * DH + n]);
            w2r[s][t][1] = f2tf32(W2[(s * 8 + c_ + 4) * DH + n]);
        }
    // Layer-1 bias permuted to d1 layout: d1[s] cols = neurons c_+8s, c_+8s+4.
    float bias1[2][2];
    #pragma unroll
    for (int s = 0; s < 2; s++) {
        bias1[s][0] = b1cs[c_ + 8 * s];
        bias1[s][1] = b1cs[c_ + 8 * s + 4];
    }
    // Layer-2 bias / layer-3 weights (natural C layout: cols t*8+2c_, +1).
    float bias2[2][2], w3r[2][2];
    #pragma unroll
    for (int t = 0; t < 2; t++) {
        int col = t * 8 + 2 * c_;
        bias2[t][0] = b2[col];  bias2[t][1] = b2[col + 1];
        w3r[t][0]   = W3[col];  w3r[t][1]   = W3[col + 1];
    }
    const float b3v = b3[0];

    // ---- hoisted addressing: each warp owns one window row ----
    const int gy  = blockIdx.x * 8 + wid;
    const int row = cy0 + gy;
    const float* pA = x + c_ * IMG_HW + row * IMG_W + cx0 + g_;
    const float* pB = ((c_ < 2) ? (x + (c_ + 4) * IMG_HW) : sigma)
                      + row * IMG_W + cx0 + g_;   // c_==3 -> its W1 rows are 0

    const long rowbase = (long)cid * PX_PER_C + gy * WS + g_ + c_ * 8;
    float* o0 = out + rowbase;
    float* o1 = out + PROB_ELEMS      + rowbase;
    float* o2 = out + 2L * PROB_ELEMS + rowbase;
    float* o3 = out + 3L * PROB_ELEMS + rowbase;
    const float fcid = (float)cid;
    const float frow = (float)row;
    const float fcolbase = (float)(cx0 + g_ + c_ * 8);

    #pragma unroll
    for (int it = 0; it < TILES_PER_WARP; it++) {
        const int o = it * TILE_PX;

        // ---- gather (rows g_, g_+8) ----
        unsigned a0 = f2tf32(pA[o]);
        unsigned a1 = f2tf32(pA[o + 8]);
        unsigned a2 = f2tf32(pB[o]);
        unsigned a3 = f2tf32(pB[o + 8]);

        // ---- layer 1: hi (bias as C) + lo (accumulate), 2 permuted n-tiles ----
        float d1[2][4];
        #pragma unroll
        for (int s = 0; s < 2; s++) {
            mma8_c(d1[s][0], d1[s][1], d1[s][2], d1[s][3],
                   a0, a1, a2, a3, w1hi[s][0], w1hi[s][1],
                   bias1[s][0], bias1[s][1], bias1[s][0], bias1[s][1]);
            mma8(d1[s][0], d1[s][1], d1[s][2], d1[s][3],
                 a0, a1, a2, a3, w1lo[s][0], w1lo[s][1]);
        }

        // ---- relu; registers ARE layer-2 A-fragments (HW tf32-truncates) ----
        unsigned A2[2][4];
        #pragma unroll
        for (int s = 0; s < 2; s++) {
            A2[s][0] = __float_as_uint(fmaxf(d1[s][0], 0.0f));  // row g_,   k c_
            A2[s][1] = __float_as_uint(fmaxf(d1[s][2], 0.0f));  // row g_+8, k c_
            A2[s][2] = __float_as_uint(fmaxf(d1[s][1], 0.0f));  // row g_,   k c_+4
            A2[s][3] = __float_as_uint(fmaxf(d1[s][3], 0.0f));  // row g_+8, k c_+4
        }

        // ---- layer 2: 2 n-tiles x 2 k-steps, bias as C on first k-step ----
        float d2[2][4];
        #pragma unroll
        for (int t = 0; t < 2; t++) {
            mma8_c(d2[t][0], d2[t][1], d2[t][2], d2[t][3],
                   A2[0][0], A2[0][1], A2[0][2], A2[0][3],
                   w2r[0][t][0], w2r[0][t][1],
                   bias2[t][0], bias2[t][1], bias2[t][0], bias2[t][1]);
            mma8(d2[t][0], d2[t][1], d2[t][2], d2[t][3],
                 A2[1][0], A2[1][1], A2[1][2], A2[1][3],
                 w2r[1][t][0], w2r[1][t][1]);
        }

        // ---- layer 3 + butterfly reduce over the quad ----
        float zg = 0.0f, z8 = 0.0f;
        #pragma unroll
        for (int t = 0; t < 2; t++) {
            zg = fmaf(fmaxf(d2[t][0], 0.0f), w3r[t][0], zg);
            zg = fmaf(fmaxf(d2[t][1], 0.0f), w3r[t][1], zg);
            z8 = fmaf(fmaxf(d2[t][2], 0.0f), w3r[t][0], z8);
            z8 = fmaf(fmaxf(d2[t][3], 0.0f), w3r[t][1], z8);
        }
        zg += __shfl_xor_sync(0xffffffffu, zg, 1);
        zg += __shfl_xor_sync(0xffffffffu, zg, 2);
        z8 += __shfl_xor_sync(0xffffffffu, z8, 1);
        z8 += __shfl_xor_sync(0xffffffffu, z8, 2);

        // ---- sigmoid + stores (c_==0 -> row g_, c_==1 -> row g_+8) ----
        if (c_ < 2) {
            float z = ((c_ == 0) ? zg : z8) + b3v;
            float p = __fdividef(1.0f, 1.0f + __expf(-z));
            o0[o] = p;
            if (write_iidd) {
                o1[o] = fcid;
                o2[o] = frow;
                o3[o] = fcolbase + (float)o;
            }
        }
    }
}

extern "C" void kernel_launch(void* const* d_in, const int* in_sizes, int n_in,
                              void* d_out, int out_size)
{
    const float* x     = (const float*)d_in[0];
    const float* sigma = (const float*)d_in[1];
    const float* cvec  = (const float*)d_in[2];
    const float* W1    = (const float*)d_in[3];
    const float* b1    = (const float*)d_in[4];
    const float* W2    = (const float*)d_in[5];
    const float* b2    = (const float*)d_in[6];
    const float* W3    = (const float*)d_in[7];
    const float* b3    = (const float*)d_in[8];
    const int*   cent  = (const int*)d_in[9];
    float* out = (float*)d_out;

    int write_iidd = (out_size >= 4 * PROB_ELEMS) ? 1 : 0;

    dim3 grid(BLOCKS_X, NC);
    instanseg_kernel<<<grid, THREADS>>>(x, sigma, cvec, W1, b1, W2, b2, W3, b3,
                                        cent, out, write_iidd);
}

// round 8
// speedup vs baseline: 2.8714x; 1.2480x over previous
#include <cuda_runtime.h>
#include <cuda_fp16.h>

#define IMG_H 1024
#define IMG_W 1024
#define IMG_HW (IMG_H * IMG_W)
#define WS 128
#define HALF 64
#define NE 6
#define NF 7
#define DH 16
#define NC 512
#define PX_PER_C (WS * WS)
#define PROB_ELEMS (NC * PX_PER_C)

#define THREADS 256          // 8 warps
#define TILE_PX 16
#define TILES_PER_WARP 8     // warp owns one 128-px window row
#define BLOCKS_X 16

// pack two f32 -> f16x2 (rn); 'lo' lands in the low half
__device__ __forceinline__ unsigned cvt2h(float lo, float hi) {
    unsigned r; asm("cvt.rn.f16x2.f32 %0, %1, %2;" : "=r"(r) : "f"(hi), "f"(lo)); return r;
}
// packed relu
__device__ __forceinline__ unsigned max2z(unsigned v) {
    unsigned r; asm("max.f16x2 %0, %1, %2;" : "=r"(r) : "r"(v), "r"(0u)); return r;
}
// d = a*b + c  (m16n8k16, f16 in, f32 accumulate, distinct C)
__device__ __forceinline__ void mma16(float& d0, float& d1, float& d2, float& d3,
                                      unsigned a0, unsigned a1, unsigned a2, unsigned a3,
                                      unsigned b0, unsigned b1,
                                      float c0, float c1, float c2, float c3) {
    asm volatile(
        "mma.sync.aligned.m16n8k16.row.col.f32.f16.f16.f32 "
        "{%0,%1,%2,%3}, {%4,%5,%6,%7}, {%8,%9}, {%10,%11,%12,%13};"
        : "=f"(d0), "=f"(d1), "=f"(d2), "=f"(d3)
        : "r"(a0), "r"(a1), "r"(a2), "r"(a3), "r"(b0), "r"(b1),
          "f"(c0), "f"(c1), "f"(c2), "f"(c3));
}

__global__ __launch_bounds__(THREADS, 3)
void instanseg_kernel(const float* __restrict__ x,
                      const float* __restrict__ sigma,
                      const float* __restrict__ cvec,
                      const float* __restrict__ W1,
                      const float* __restrict__ b1,
                      const float* __restrict__ W2,
                      const float* __restrict__ b2,
                      const float* __restrict__ W3,
                      const float* __restrict__ b3,
                      const int*   __restrict__ cent,
                      float* __restrict__ out,
                      int write_iidd)
{
    __shared__ float b1cs[DH];     // b1 - c[cid] @ W1[0:6]
    __shared__ int   cy0s, cx0s;

    const int tid  = threadIdx.x;
    const int wid  = tid >> 5;
    const int lane = tid & 31;
    const int g_   = lane >> 2;
    const int c_   = lane & 3;
    const int cid  = blockIdx.y;

    if (tid < DH) {
        float acc = b1[tid];
        #pragma unroll
        for (int e = 0; e < NE; e++)
            acc -= cvec[cid * NE + e] * W1[e * DH + tid];
        b1cs[tid] = acc;
    }
    if (tid == 0) {
        int cy = cent[cid * 2 + 0];
        int cx = cent[cid * 2 + 1];
        cy = min(max(cy, HALF), IMG_H - HALF);
        cx = min(max(cx, HALF), IMG_W - HALF);
        cy0s = cy - HALF;
        cx0s = cx - HALF;
    }
    __syncthreads();

    const int cy0 = cy0s, cx0 = cx0s;

    // ---- W1 fragments: k-slots 0..7 = hi weights, 8..15 = lo residuals.
    // Activations are duplicated into slots 8..15 (a2=a0,a3=a1) -> exact
    // fp32 weights in a SINGLE k16 MMA per n-tile. Feature 7 rows are 0.
    unsigned w1f[2][2];
    float bias1[2][2];
    #pragma unroll
    for (int t = 0; t < 2; t++) {
        int n = 8 * t + g_;
        float w0 = W1[(2 * c_) * DH + n];
        float w1v = (2 * c_ + 1 < NF) ? W1[(2 * c_ + 1) * DH + n] : 0.0f;
        float h0 = __half2float(__float2half_rn(w0));
        float h1 = __half2float(__float2half_rn(w1v));
        w1f[t][0] = cvt2h(w0, w1v);            // hi pair  (k=2c_, 2c_+1)
        w1f[t][1] = cvt2h(w0 - h0, w1v - h1);  // lo pair  (k=2c_+8, 2c_+9)
        bias1[t][0] = b1cs[8 * t + 2 * c_];
        bias1[t][1] = b1cs[8 * t + 2 * c_ + 1];
    }
    // W2 fragments (single fp16 rn), natural layout.
    unsigned w2f[2][2];
    float bias2[2][2];
    #pragma unroll
    for (int t = 0; t < 2; t++) {
        int n = 8 * t + g_;
        w2f[t][0] = cvt2h(W2[(2 * c_)     * DH + n], W2[(2 * c_ + 1) * DH + n]);
        w2f[t][1] = cvt2h(W2[(2 * c_ + 8) * DH + n], W2[(2 * c_ + 9) * DH + n]);
        bias2[t][0] = b2[8 * t + 2 * c_];
        bias2[t][1] = b2[8 * t + 2 * c_ + 1];
    }
    // W3 fragment (layer 3 as MMA: every n-col identical -> z broadcast to all lanes)
    unsigned w3f[2];
    w3f[0] = cvt2h(W3[2 * c_],     W3[2 * c_ + 1]);
    w3f[1] = cvt2h(W3[2 * c_ + 8], W3[2 * c_ + 9]);
    const float b3v = b3[0];

    // ---- addressing: each warp owns one window row; thread owns feature
    // planes 2c_ and 2c_+1 (plane 7 = junk, weight rows are zero).
    const int gy  = blockIdx.x * 8 + wid;
    const int row = cy0 + gy;
    const float* pA = ((2 * c_     < NE) ? (x + (2 * c_)     * IMG_HW) : sigma)
                      + row * IMG_W + cx0 + g_;
    const float* pB = ((2 * c_ + 1 < NE) ? (x + (2 * c_ + 1) * IMG_HW) : sigma)
                      + row * IMG_W + cx0 + g_;

    const long rowbase = (long)cid * PX_PER_C + gy * WS + g_ + c_ * 8;
    float* o0 = out + rowbase;
    float* o1 = out + PROB_ELEMS      + rowbase;
    float* o2 = out + 2L * PROB_ELEMS + rowbase;
    float* o3 = out + 3L * PROB_ELEMS + rowbase;
    const float fcid = (float)cid;
    const float frow = (float)row;
    const float fcolbase = (float)(cx0 + g_ + c_ * 8);

    #pragma unroll
    for (int it = 0; it < TILES_PER_WARP; it++) {
        const int o = it * TILE_PX;

        // ---- gather + pack (rows g_, g_+8; features 2c_, 2c_+1) ----
        unsigned a0 = cvt2h(pA[o],     pB[o]);      // row g_
        unsigned a1 = cvt2h(pA[o + 8], pB[o + 8]);  // row g_+8

        // ---- layer 1: ONE k16 MMA per n-tile (hi+lo folded, bias as C) ----
        float d1[2][4];
        #pragma unroll
        for (int t = 0; t < 2; t++)
            mma16(d1[t][0], d1[t][1], d1[t][2], d1[t][3],
                  a0, a1, a0, a1,             // k 8..15 duplicate activations
                  w1f[t][0], w1f[t][1],
                  bias1[t][0], bias1[t][1], bias1[t][0], bias1[t][1]);

        // ---- relu + pack: d1 tiles ARE the k16 A-fragment (natural order) ----
        unsigned A0 = max2z(cvt2h(d1[0][0], d1[0][1]));  // row g_,   k 2c_,2c_+1
        unsigned A1 = max2z(cvt2h(d1[0][2], d1[0][3]));  // row g_+8
        unsigned A2 = max2z(cvt2h(d1[1][0], d1[1][1]));  // row g_,   k 2c_+8,+9
        unsigned A3 = max2z(cvt2h(d1[1][2], d1[1][3]));  // row g_+8

        // ---- layer 2: ONE k16 MMA per n-tile (bias as C) ----
        float d2[2][4];
        #pragma unroll
        for (int t = 0; t < 2; t++)
            mma16(d2[t][0], d2[t][1], d2[t][2], d2[t][3],
                  A0, A1, A2, A3, w2f[t][0], w2f[t][1],
                  bias2[t][0], bias2[t][1], bias2[t][0], bias2[t][1]);

        // ---- relu + pack for layer 3 ----
        unsigned B0 = max2z(cvt2h(d2[0][0], d2[0][1]));
        unsigned B1 = max2z(cvt2h(d2[0][2], d2[0][3]));
        unsigned B2 = max2z(cvt2h(d2[1][0], d2[1][1]));
        unsigned B3 = max2z(cvt2h(d2[1][2], d2[1][3]));

        // ---- layer 3 as MMA: all 8 n-cols identical -> no reduce, no shfl ----
        float d3[4];
        mma16(d3[0], d3[1], d3[2], d3[3],
              B0, B1, B2, B3, w3f[0], w3f[1],
              b3v, b3v, b3v, b3v);
        // z(row g_) = d3[0], z(row g_+8) = d3[2], in every lane.

        // ---- sigmoid + stores (c_==0 -> row g_, c_==1 -> row g_+8) ----
        float z = (c_ == 0) ? d3[0] : d3[2];
        float p = __fdividef(1.0f, 1.0f + __expf(-z));
        if (c_ < 2) {
            o0[o] = p;
            if (write_iidd) {
                o1[o] = fcid;
                o2[o] = frow;
                o3[o] = fcolbase + (float)o;
            }
        }
    }
}

extern "C" void kernel_launch(void* const* d_in, const int* in_sizes, int n_in,
                              void* d_out, int out_size)
{
    const float* x     = (const float*)d_in[0];
    const float* sigma = (const float*)d_in[1];
    const float* cvec  = (const float*)d_in[2];
    const float* W1    = (const float*)d_in[3];
    const float* b1    = (const float*)d_in[4];
    const float* W2    = (const float*)d_in[5];
    const float* b2    = (const float*)d_in[6];
    const float* W3    = (const float*)d_in[7];
    const float* b3    = (const float*)d_in[8];
    const int*   cent  = (const int*)d_in[9];
    float* out = (float*)d_out;

    int write_iidd = (out_size >= 4 * PROB_ELEMS) ? 1 : 0;

    dim3 grid(BLOCKS_X, NC);
    instanseg_kernel<<<grid, THREADS>>>(x, sigma, cvec, W1, b1, W2, b2, W3, b3,
                                        cent, out, write_iidd);
}

// round 9
// speedup vs baseline: 3.0177x; 1.0510x over previous
#include <cuda_runtime.h>
#include <cuda_fp16.h>

#define IMG_H 1024
#define IMG_W 1024
#define IMG_HW (IMG_H * IMG_W)
#define WS 128
#define HALF 64
#define NE 6
#define NF 7
#define DH 16
#define NC 512
#define PX_PER_C (WS * WS)
#define PROB_ELEMS (NC * PX_PER_C)

#define THREADS 256          // 8 warps; each warp owns one window row
#define BLOCKS_X 16
#define PAD 132              // 132 % 16 == 4 -> conflict-free LDS.64 reads

// pack two f32 -> f16x2 (rn); first arg lands in the LOW half
__device__ __forceinline__ unsigned cvt2h(float lo, float hi) {
    unsigned r; asm("cvt.rn.f16x2.f32 %0, %1, %2;" : "=r"(r) : "f"(hi), "f"(lo)); return r;
}
__device__ __forceinline__ unsigned max2z(unsigned v) {
    unsigned r; asm("max.f16x2 %0, %1, %2;" : "=r"(r) : "r"(v), "r"(0u)); return r;
}
// d = a*b + c  (m16n8k16, f16 in, f32 accumulate, distinct C)
__device__ __forceinline__ void mma16(float& d0, float& d1, float& d2, float& d3,
                                      unsigned a0, unsigned a1, unsigned a2, unsigned a3,
                                      unsigned b0, unsigned b1,
                                      float c0, float c1, float c2, float c3) {
    asm volatile(
        "mma.sync.aligned.m16n8k16.row.col.f32.f16.f16.f32 "
        "{%0,%1,%2,%3}, {%4,%5,%6,%7}, {%8,%9}, {%10,%11,%12,%13};"
        : "=f"(d0), "=f"(d1), "=f"(d2), "=f"(d3)
        : "r"(a0), "r"(a1), "r"(a2), "r"(a3), "r"(b0), "r"(b1),
          "f"(c0), "f"(c1), "f"(c2), "f"(c3));
}

__global__ __launch_bounds__(THREADS, 3)
void instanseg_kernel(const float* __restrict__ x,
                      const float* __restrict__ sigma,
                      const float* __restrict__ cvec,
                      const float* __restrict__ W1,
                      const float* __restrict__ b1,
                      const float* __restrict__ W2,
                      const float* __restrict__ b2,
                      const float* __restrict__ W3,
                      const float* __restrict__ b3,
                      const int*   __restrict__ cent,
                      float* __restrict__ out,
                      int write_iidd)
{
    __shared__ float b1cs[DH];            // b1 - c[cid] @ W1[0:6]
    __shared__ float fbuf[8][8][PAD];     // [warp][feature][px]; f=7 zeroed
    __shared__ int   cy0s, cx0s;

    const int tid  = threadIdx.x;
    const int wid  = tid >> 5;
    const int lane = tid & 31;
    const int g_   = lane >> 2;
    const int c_   = lane & 3;
    const int cid  = blockIdx.y;

    if (tid < DH) {
        float acc = b1[tid];
        #pragma unroll
        for (int e = 0; e < NE; e++)
            acc -= cvec[cid * NE + e] * W1[e * DH + tid];
        b1cs[tid] = acc;
    }
    if (tid == 0) {
        int cy = cent[cid * 2 + 0];
        int cx = cent[cid * 2 + 1];
        cy = min(max(cy, HALF), IMG_H - HALF);
        cx = min(max(cx, HALF), IMG_W - HALF);
        cy0s = cy - HALF;
        cx0s = cx - HALF;
    }
    __syncthreads();

    const int cy0 = cy0s, cx0 = cx0s;

    // ---- weight fragments (identical to R8) ----
    // W1: k 0..7 = fp16 hi weights, k 8..15 = lo residuals; activations get
    // duplicated into k 8..15 -> exact fp32 W1 in one k16 MMA per n-tile.
    unsigned w1f[2][2];
    float bias1[2][2];
    #pragma unroll
    for (int t = 0; t < 2; t++) {
        int n = 8 * t + g_;
        float w0  = W1[(2 * c_) * DH + n];
        float w1v = (2 * c_ + 1 < NF) ? W1[(2 * c_ + 1) * DH + n] : 0.0f;
        float h0 = __half2float(__float2half_rn(w0));
        float h1 = __half2float(__float2half_rn(w1v));
        w1f[t][0] = cvt2h(w0, w1v);
        w1f[t][1] = cvt2h(w0 - h0, w1v - h1);
        bias1[t][0] = b1cs[8 * t + 2 * c_];
        bias1[t][1] = b1cs[8 * t + 2 * c_ + 1];
    }
    unsigned w2f[2][2];
    float bias2[2][2];
    #pragma unroll
    for (int t = 0; t < 2; t++) {
        int n = 8 * t + g_;
        w2f[t][0] = cvt2h(W2[(2 * c_)     * DH + n], W2[(2 * c_ + 1) * DH + n]);
        w2f[t][1] = cvt2h(W2[(2 * c_ + 8) * DH + n], W2[(2 * c_ + 9) * DH + n]);
        bias2[t][0] = b2[8 * t + 2 * c_];
        bias2[t][1] = b2[8 * t + 2 * c_ + 1];
    }
    unsigned w3f[2];
    w3f[0] = cvt2h(W3[2 * c_],     W3[2 * c_ + 1]);
    w3f[1] = cvt2h(W3[2 * c_ + 8], W3[2 * c_ + 9]);
    const float b3v = b3[0];

    // ---- stage this warp's row: 7 planes x 128 cols, coalesced ----
    const int gy  = blockIdx.x * 8 + wid;
    const int row = cy0 + gy;
    float* fw = &fbuf[wid][0][0];
    #pragma unroll
    for (int f = 0; f < 7; f++) {
        const float* pf = ((f < NE) ? (x + f * IMG_HW) : sigma)
                          + row * IMG_W + cx0;
        #pragma unroll
        for (int q = 0; q < 4; q++)
            fw[f * PAD + q * 32 + lane] = pf[q * 32 + lane];   // banks == lane
    }
    #pragma unroll
    for (int q = 0; q < 4; q++)
        fw[7 * PAD + q * 32 + lane] = 0.0f;   // zero pad plane (W1 row 7 == 0)
    __syncwarp();

    const long rowstart = (long)cid * PX_PER_C + (long)gy * WS;
    float* oprob = out + rowstart;

    // pixel-pair permutation: MMA row g_ <-> px o+2g_, row g_+8 <-> px o+2g_+1
    const float* fA = fw + (2 * c_) * PAD + 2 * g_;       // feature 2c_
    const float* fB = fw + (2 * c_ + 1) * PAD + 2 * g_;   // feature 2c_+1

    #pragma unroll
    for (int it = 0; it < 8; it++) {
        const int o = it * 16;

        // ---- A-operands from smem: two conflict-free LDS.64 ----
        float2 u = *(const float2*)(fA + o);
        float2 v = *(const float2*)(fB + o);
        unsigned a0 = cvt2h(u.x, v.x);   // row g_   = px o+2g_
        unsigned a1 = cvt2h(u.y, v.y);   // row g_+8 = px o+2g_+1

        // ---- layer 1: one k16 MMA per n-tile (hi+lo folded, bias as C) ----
        float d1[2][4];
        #pragma unroll
        for (int t = 0; t < 2; t++)
            mma16(d1[t][0], d1[t][1], d1[t][2], d1[t][3],
                  a0, a1, a0, a1,
                  w1f[t][0], w1f[t][1],
                  bias1[t][0], bias1[t][1], bias1[t][0], bias1[t][1]);

        // ---- relu + pack: d1 tiles ARE the k16 A-fragment ----
        unsigned A0 = max2z(cvt2h(d1[0][0], d1[0][1]));
        unsigned A1 = max2z(cvt2h(d1[0][2], d1[0][3]));
        unsigned A2 = max2z(cvt2h(d1[1][0], d1[1][1]));
        unsigned A3 = max2z(cvt2h(d1[1][2], d1[1][3]));

        // ---- layer 2 ----
        float d2[2][4];
        #pragma unroll
        for (int t = 0; t < 2; t++)
            mma16(d2[t][0], d2[t][1], d2[t][2], d2[t][3],
                  A0, A1, A2, A3, w2f[t][0], w2f[t][1],
                  bias2[t][0], bias2[t][1], bias2[t][0], bias2[t][1]);

        // ---- relu + pack for layer 3 ----
        unsigned B0 = max2z(cvt2h(d2[0][0], d2[0][1]));
        unsigned B1 = max2z(cvt2h(d2[0][2], d2[0][3]));
        unsigned B2 = max2z(cvt2h(d2[1][0], d2[1][1]));
        unsigned B3 = max2z(cvt2h(d2[1][2], d2[1][3]));

        // ---- layer 3 as MMA: z broadcast to all lanes of the quad ----
        float d3[4];
        mma16(d3[0], d3[1], d3[2], d3[3],
              B0, B1, B2, B3, w3f[0], w3f[1],
              b3v, b3v, b3v, b3v);

        // ---- sigmoid + adjacent-pair store (one 64B wavefront/tile) ----
        if (c_ == 0) {
            float p0 = __fdividef(1.0f, 1.0f + __expf(-d3[0]));
            float p1 = __fdividef(1.0f, 1.0f + __expf(-d3[2]));
            *(float2*)(oprob + o + 2 * g_) = make_float2(p0, p1);
        }
    }

    // ---- iidd: pure index math, three coalesced STG.128 per row ----
    if (write_iidd) {
        const float fcid = (float)cid;
        const float frow = (float)row;
        const float fc0  = (float)(cx0 + 4 * lane);
        float4 vc = make_float4(fcid, fcid, fcid, fcid);
        float4 vr = make_float4(frow, frow, frow, frow);
        float4 vx = make_float4(fc0, fc0 + 1.0f, fc0 + 2.0f, fc0 + 3.0f);
        *(float4*)(out + PROB_ELEMS      + rowstart + 4 * lane) = vc;
        *(float4*)(out + 2L * PROB_ELEMS + rowstart + 4 * lane) = vr;
        *(float4*)(out + 3L * PROB_ELEMS + rowstart + 4 * lane) = vx;
    }
}

extern "C" void kernel_launch(void* const* d_in, const int* in_sizes, int n_in,
                              void* d_out, int out_size)
{
    const float* x     = (const float*)d_in[0];
    const float* sigma = (const float*)d_in[1];
    const float* cvec  = (const float*)d_in[2];
    const float* W1    = (const float*)d_in[3];
    const float* b1    = (const float*)d_in[4];
    const float* W2    = (const float*)d_in[5];
    const float* b2    = (const float*)d_in[6];
    const float* W3    = (const float*)d_in[7];
    const float* b3    = (const float*)d_in[8];
    const int*   cent  = (const int*)d_in[9];
    float* out = (float*)d_out;

    int write_iidd = (out_size >= 4 * PROB_ELEMS) ? 1 : 0;

    dim3 grid(BLOCKS_X, NC);
    instanseg_kernel<<<grid, THREADS>>>(x, sigma, cvec, W1, b1, W2, b2, W3, b3,
                                        cent, out, write_iidd);
}

// round 10
// speedup vs baseline: 3.4297x; 1.1365x over previous
#include <cuda_runtime.h>
#include <cuda_fp16.h>

#define IMG_H 1024
#define IMG_W 1024
#define IMG_HW (IMG_H * IMG_W)
#define WS 128
#define HALF 64
#define NE 6
#define NF 7
#define DH 16
#define NC 512
#define PX_PER_C (WS * WS)
#define PROB_ELEMS (NC * PX_PER_C)

#define THREADS 256          // 8 warps; each warp owns one window row
#define BLOCKS_X 16
#define PAD 132              // conflict-free LDS.64 reads

// pack two f32 -> f16x2 (rn); first arg lands in the LOW half
__device__ __forceinline__ unsigned cvt2h(float lo, float hi) {
    unsigned r; asm("cvt.rn.f16x2.f32 %0, %1, %2;" : "=r"(r) : "f"(hi), "f"(lo)); return r;
}
__device__ __forceinline__ unsigned max2z(unsigned v) {
    unsigned r; asm("max.f16x2 %0, %1, %2;" : "=r"(r) : "r"(v), "r"(0u)); return r;
}
// m16n8k8, all-f16: D,C packed f16x2 (d0=row g cols{2c,2c+1}, d1=row g+8)
__device__ __forceinline__ void mma8h(unsigned& d0, unsigned& d1,
                                      unsigned a0, unsigned a1,
                                      unsigned b0,
                                      unsigned c0, unsigned c1) {
    asm volatile(
        "mma.sync.aligned.m16n8k8.row.col.f16.f16.f16.f16 "
        "{%0,%1}, {%2,%3}, {%4}, {%5,%6};"
        : "=r"(d0), "=r"(d1)
        : "r"(a0), "r"(a1), "r"(b0), "r"(c0), "r"(c1));
}
// m16n8k16, all-f16
__device__ __forceinline__ void mma16h(unsigned& d0, unsigned& d1,
                                       unsigned a0, unsigned a1, unsigned a2, unsigned a3,
                                       unsigned b0, unsigned b1,
                                       unsigned c0, unsigned c1) {
    asm volatile(
        "mma.sync.aligned.m16n8k16.row.col.f16.f16.f16.f16 "
        "{%0,%1}, {%2,%3,%4,%5}, {%6,%7}, {%8,%9};"
        : "=r"(d0), "=r"(d1)
        : "r"(a0), "r"(a1), "r"(a2), "r"(a3), "r"(b0), "r"(b1), "r"(c0), "r"(c1));
}
// m16n8k16, f16 in, f32 accumulate (final layer)
__device__ __forceinline__ void mma16f(float& d0, float& d1, float& d2, float& d3,
                                       unsigned a0, unsigned a1, unsigned a2, unsigned a3,
                                       unsigned b0, unsigned b1,
                                       float c0, float c1, float c2, float c3) {
    asm volatile(
        "mma.sync.aligned.m16n8k16.row.col.f32.f16.f16.f32 "
        "{%0,%1,%2,%3}, {%4,%5,%6,%7}, {%8,%9}, {%10,%11,%12,%13};"
        : "=f"(d0), "=f"(d1), "=f"(d2), "=f"(d3)
        : "r"(a0), "r"(a1), "r"(a2), "r"(a3), "r"(b0), "r"(b1),
          "f"(c0), "f"(c1), "f"(c2), "f"(c3));
}

__global__ __launch_bounds__(THREADS, 4)
void instanseg_kernel(const float* __restrict__ x,
                      const float* __restrict__ sigma,
                      const float* __restrict__ cvec,
                      const float* __restrict__ W1,
                      const float* __restrict__ b1,
                      const float* __restrict__ W2,
                      const float* __restrict__ b2,
                      const float* __restrict__ W3,
                      const float* __restrict__ b3,
                      const int*   __restrict__ cent,
                      float* __restrict__ out,
                      int write_iidd)
{
    __shared__ float b1cs[DH];            // b1 - c[cid] @ W1[0:6]
    __shared__ float fbuf[8][8][PAD];     // [warp][feature][px]; f=7 zeroed
    __shared__ int   cy0s, cx0s;

    const int tid  = threadIdx.x;
    const int wid  = tid >> 5;
    const int lane = tid & 31;
    const int g_   = lane >> 2;
    const int c_   = lane & 3;
    const int cid  = blockIdx.y;

    if (tid < DH) {
        float acc = b1[tid];
        #pragma unroll
        for (int e = 0; e < NE; e++)
            acc -= cvec[cid * NE + e] * W1[e * DH + tid];
        b1cs[tid] = acc;
    }
    if (tid == 0) {
        int cy = cent[cid * 2 + 0];
        int cx = cent[cid * 2 + 1];
        cy = min(max(cy, HALF), IMG_H - HALF);
        cx = min(max(cx, HALF), IMG_W - HALF);
        cy0s = cy - HALF;
        cx0s = cx - HALF;
    }
    __syncthreads();

    const int cy0 = cy0s, cx0 = cx0s;

    // ---- weight fragments (all packed f16x2) ----
    // Layer 1 (k8): B reg = W1 rows {2c_,2c_+1} at out-col n=8t+g_; row 7 -> 0.
    unsigned w1f[2], bias1h[2];
    #pragma unroll
    for (int t = 0; t < 2; t++) {
        int n = 8 * t + g_;
        float w0  = W1[(2 * c_) * DH + n];
        float w1v = (2 * c_ + 1 < NF) ? W1[(2 * c_ + 1) * DH + n] : 0.0f;
        w1f[t] = cvt2h(w0, w1v);
        bias1h[t] = cvt2h(b1cs[8 * t + 2 * c_], b1cs[8 * t + 2 * c_ + 1]);
    }
    // Layer 2 (k16)
    unsigned w2f[2][2], bias2h[2];
    #pragma unroll
    for (int t = 0; t < 2; t++) {
        int n = 8 * t + g_;
        w2f[t][0] = cvt2h(W2[(2 * c_)     * DH + n], W2[(2 * c_ + 1) * DH + n]);
        w2f[t][1] = cvt2h(W2[(2 * c_ + 8) * DH + n], W2[(2 * c_ + 9) * DH + n]);
        bias2h[t] = cvt2h(b2[8 * t + 2 * c_], b2[8 * t + 2 * c_ + 1]);
    }
    // Layer 3 (k16, f32 accum); all n-cols identical -> z broadcast
    unsigned w3f[2];
    w3f[0] = cvt2h(W3[2 * c_],     W3[2 * c_ + 1]);
    w3f[1] = cvt2h(W3[2 * c_ + 8], W3[2 * c_ + 9]);
    const float b3v = b3[0];

    // ---- stage this warp's row: 7 planes x 128 cols, coalesced ----
    const int gy  = blockIdx.x * 8 + wid;
    const int row = cy0 + gy;
    float* fw = &fbuf[wid][0][0];
    #pragma unroll
    for (int f = 0; f < 7; f++) {
        const float* pf = ((f < NE) ? (x + f * IMG_HW) : sigma)
                          + row * IMG_W + cx0;
        #pragma unroll
        for (int q = 0; q < 4; q++)
            fw[f * PAD + q * 32 + lane] = pf[q * 32 + lane];
    }
    #pragma unroll
    for (int q = 0; q < 4; q++)
        fw[7 * PAD + q * 32 + lane] = 0.0f;   // pad plane (W1 row 7 == 0)
    __syncwarp();

    const long rowstart = (long)cid * PX_PER_C + (long)gy * WS;
    float* oprob = out + rowstart;

    // pixel-pair permutation: MMA row g_ <-> px o+2g_, row g_+8 <-> px o+2g_+1
    const float* fA = fw + (2 * c_) * PAD + 2 * g_;       // feature 2c_
    const float* fB = fw + (2 * c_ + 1) * PAD + 2 * g_;   // feature 2c_+1

    #pragma unroll
    for (int it = 0; it < 8; it++) {
        const int o = it * 16;

        // ---- A-operands: two conflict-free LDS.64 + two packs ----
        float2 u = *(const float2*)(fA + o);
        float2 v = *(const float2*)(fB + o);
        unsigned a0 = cvt2h(u.x, v.x);   // row g_   = px o+2g_
        unsigned a1 = cvt2h(u.y, v.y);   // row g_+8 = px o+2g_+1

        // ---- layer 1: k8, f16-out (bias as C) ----
        unsigned d1[2][2];
        #pragma unroll
        for (int t = 0; t < 2; t++)
            mma8h(d1[t][0], d1[t][1], a0, a1, w1f[t], bias1h[t], bias1h[t]);

        // relu; packed D regs ARE the next A-fragment
        unsigned A0 = max2z(d1[0][0]);
        unsigned A1 = max2z(d1[0][1]);
        unsigned A2 = max2z(d1[1][0]);
        unsigned A3 = max2z(d1[1][1]);

        // ---- layer 2: k16, f16-out (bias as C) ----
        unsigned d2[2][2];
        #pragma unroll
        for (int t = 0; t < 2; t++)
            mma16h(d2[t][0], d2[t][1], A0, A1, A2, A3,
                   w2f[t][0], w2f[t][1], bias2h[t], bias2h[t]);

        unsigned B0 = max2z(d2[0][0]);
        unsigned B1 = max2z(d2[0][1]);
        unsigned B2 = max2z(d2[1][0]);
        unsigned B3 = max2z(d2[1][1]);

        // ---- layer 3: k16, f32 accum; z broadcast to all lanes ----
        float d3[4];
        mma16f(d3[0], d3[1], d3[2], d3[3],
               B0, B1, B2, B3, w3f[0], w3f[1],
               b3v, b3v, b3v, b3v);

        // ---- sigmoid + adjacent-pair store ----
        if (c_ == 0) {
            float p0 = __fdividef(1.0f, 1.0f + __expf(-d3[0]));
            float p1 = __fdividef(1.0f, 1.0f + __expf(-d3[2]));
            *(float2*)(oprob + o + 2 * g_) = make_float2(p0, p1);
        }
    }

    // ---- iidd: pure index math, three coalesced STG.128 per row ----
    if (write_iidd) {
        const float fcid = (float)cid;
        const float frow = (float)row;
        const float fc0  = (float)(cx0 + 4 * lane);
        float4 vc = make_float4(fcid, fcid, fcid, fcid);
        float4 vr = make_float4(frow, frow, frow, frow);
        float4 vx = make_float4(fc0, fc0 + 1.0f, fc0 + 2.0f, fc0 + 3.0f);
        *(float4*)(out + PROB_ELEMS      + rowstart + 4 * lane) = vc;
        *(float4*)(out + 2L * PROB_ELEMS + rowstart + 4 * lane) = vr;
        *(float4*)(out + 3L * PROB_ELEMS + rowstart + 4 * lane) = vx;
    }
}

extern "C" void kernel_launch(void* const* d_in, const int* in_sizes, int n_in,
                              void* d_out, int out_size)
{
    const float* x     = (const float*)d_in[0];
    const float* sigma = (const float*)d_in[1];
    const float* cvec  = (const float*)d_in[2];
    const float* W1    = (const float*)d_in[3];
    const float* b1    = (const float*)d_in[4];
    const float* W2    = (const float*)d_in[5];
    const float* b2    = (const float*)d_in[6];
    const float* W3    = (const float*)d_in[7];
    const float* b3    = (const float*)d_in[8];
    const int*   cent  = (const int*)d_in[9];
    float* out = (float*)d_out;

    int write_iidd = (out_size >= 4 * PROB_ELEMS) ? 1 : 0;

    dim3 grid(BLOCKS_X, NC);
    instanseg_kernel<<<grid, THREADS>>>(x, sigma, cvec, W1, b1, W2, b2, W3, b3,
                                        cent, out, write_iidd);
}

// round 11
// speedup vs baseline: 3.7613x; 1.0967x over previous
#include <cuda_runtime.h>
#include <cuda_fp16.h>

#define IMG_H 1024
#define IMG_W 1024
#define IMG_HW (IMG_H * IMG_W)
#define WS 128
#define HALF 64
#define NE 6
#define NF 7
#define DH 16
#define NC 512
#define PX_PER_C (WS * WS)
#define PROB_ELEMS (NC * PX_PER_C)

#define THREADS 256          // 8 warps; each warp owns one window row
#define BLOCKS_X 16
#define PADW 136             // half2 words per pair-plane: conflict-free LDS.64

// pack two f32 -> f16x2 (rn); first arg lands in the LOW half
__device__ __forceinline__ unsigned cvt2h(float lo, float hi) {
    unsigned r; asm("cvt.rn.f16x2.f32 %0, %1, %2;" : "=r"(r) : "f"(hi), "f"(lo)); return r;
}
__device__ __forceinline__ unsigned max2z(unsigned v) {
    unsigned r; asm("max.f16x2 %0, %1, %2;" : "=r"(r) : "r"(v), "r"(0u)); return r;
}
// m16n8k8, all-f16
__device__ __forceinline__ void mma8h(unsigned& d0, unsigned& d1,
                                      unsigned a0, unsigned a1,
                                      unsigned b0,
                                      unsigned c0, unsigned c1) {
    asm volatile(
        "mma.sync.aligned.m16n8k8.row.col.f16.f16.f16.f16 "
        "{%0,%1}, {%2,%3}, {%4}, {%5,%6};"
        : "=r"(d0), "=r"(d1)
        : "r"(a0), "r"(a1), "r"(b0), "r"(c0), "r"(c1));
}
// m16n8k16, all-f16
__device__ __forceinline__ void mma16h(unsigned& d0, unsigned& d1,
                                       unsigned a0, unsigned a1, unsigned a2, unsigned a3,
                                       unsigned b0, unsigned b1,
                                       unsigned c0, unsigned c1) {
    asm volatile(
        "mma.sync.aligned.m16n8k16.row.col.f16.f16.f16.f16 "
        "{%0,%1}, {%2,%3,%4,%5}, {%6,%7}, {%8,%9};"
        : "=r"(d0), "=r"(d1)
        : "r"(a0), "r"(a1), "r"(a2), "r"(a3), "r"(b0), "r"(b1), "r"(c0), "r"(c1));
}
// m16n8k16, f16 in, f32 accumulate (final layer)
__device__ __forceinline__ void mma16f(float& d0, float& d1, float& d2, float& d3,
                                       unsigned a0, unsigned a1, unsigned a2, unsigned a3,
                                       unsigned b0, unsigned b1,
                                       float c0, float c1, float c2, float c3) {
    asm volatile(
        "mma.sync.aligned.m16n8k16.row.col.f32.f16.f16.f32 "
        "{%0,%1,%2,%3}, {%4,%5,%6,%7}, {%8,%9}, {%10,%11,%12,%13};"
        : "=f"(d0), "=f"(d1), "=f"(d2), "=f"(d3)
        : "r"(a0), "r"(a1), "r"(a2), "r"(a3), "r"(b0), "r"(b1),
          "f"(c0), "f"(c1), "f"(c2), "f"(c3));
}

__global__ __launch_bounds__(THREADS, 4)
void instanseg_kernel(const float* __restrict__ x,
                      const float* __restrict__ sigma,
                      const float* __restrict__ cvec,
                      const float* __restrict__ W1,
                      const float* __restrict__ b1,
                      const float* __restrict__ W2,
                      const float* __restrict__ b2,
                      const float* __restrict__ W3,
                      const float* __restrict__ b3,
                      const int*   __restrict__ cent,
                      float* __restrict__ out,
                      int write_iidd)
{
    __shared__ float    b1cs[DH];            // b1 - c[cid] @ W1[0:6]
    __shared__ unsigned h2buf[8][4 * PADW];  // [warp][pair-plane][px] packed half2
    __shared__ int      cy0s, cx0s;

    const int tid  = threadIdx.x;
    const int wid  = tid >> 5;
    const int lane = tid & 31;
    const int g_   = lane >> 2;
    const int c_   = lane & 3;
    const int cid  = blockIdx.y;

    if (tid < DH) {
        float acc = b1[tid];
        #pragma unroll
        for (int e = 0; e < NE; e++)
            acc -= cvec[cid * NE + e] * W1[e * DH + tid];
        b1cs[tid] = acc;
    }
    if (tid == 0) {
        int cy = cent[cid * 2 + 0];
        int cx = cent[cid * 2 + 1];
        cy = min(max(cy, HALF), IMG_H - HALF);
        cx = min(max(cx, HALF), IMG_W - HALF);
        cy0s = cy - HALF;
        cx0s = cx - HALF;
    }
    __syncthreads();

    const int cy0 = cy0s, cx0 = cx0s;

    // ---- weight fragments (packed f16x2) ----
    unsigned w1f[2], bias1h[2];
    #pragma unroll
    for (int t = 0; t < 2; t++) {
        int n = 8 * t + g_;
        float w0  = W1[(2 * c_) * DH + n];
        float w1v = (2 * c_ + 1 < NF) ? W1[(2 * c_ + 1) * DH + n] : 0.0f;
        w1f[t] = cvt2h(w0, w1v);
        bias1h[t] = cvt2h(b1cs[8 * t + 2 * c_], b1cs[8 * t + 2 * c_ + 1]);
    }
    unsigned w2f[2][2], bias2h[2];
    #pragma unroll
    for (int t = 0; t < 2; t++) {
        int n = 8 * t + g_;
        w2f[t][0] = cvt2h(W2[(2 * c_)     * DH + n], W2[(2 * c_ + 1) * DH + n]);
        w2f[t][1] = cvt2h(W2[(2 * c_ + 8) * DH + n], W2[(2 * c_ + 9) * DH + n]);
        bias2h[t] = cvt2h(b2[8 * t + 2 * c_], b2[8 * t + 2 * c_ + 1]);
    }
    unsigned w3f[2];
    w3f[0] = cvt2h(W3[2 * c_],     W3[2 * c_ + 1]);
    w3f[1] = cvt2h(W3[2 * c_ + 8], W3[2 * c_ + 9]);
    const float b3v = b3[0];

    // ---- stage this warp's row as PRE-PACKED half2 feature pairs ----
    // h2buf[wid][p*PADW + px] = half2(feat_{2p}(px), feat_{2p+1}(px)); p=3 -> (sigma, 0)
    const int gy  = blockIdx.x * 8 + wid;
    const int row = cy0 + gy;
    unsigned* fw = h2buf[wid];
    {
        const long roff = (long)row * IMG_W + cx0;
        #pragma unroll
        for (int p = 0; p < 3; p++) {
            const float* f0 = x + (2 * p)     * IMG_HW + roff;
            const float* f1 = x + (2 * p + 1) * IMG_HW + roff;
            #pragma unroll
            for (int q = 0; q < 4; q++) {
                int col = q * 32 + lane;
                fw[p * PADW + col] = cvt2h(f0[col], f1[col]);   // banks == lane
            }
        }
        const float* fs = sigma + roff;
        #pragma unroll
        for (int q = 0; q < 4; q++) {
            int col = q * 32 + lane;
            fw[3 * PADW + col] = cvt2h(fs[col], 0.0f);
        }
    }
    __syncwarp();

    const long rowstart = (long)cid * PX_PER_C + (long)gy * WS;
    float* oprob = out + rowstart;

    // pixel-pair permutation: MMA row g_ <-> px o+2g_, row g_+8 <-> px o+2g_+1
    // thread's A operands = adjacent half2s -> single LDS.64 per tile
    const unsigned* fp = fw + c_ * PADW + 2 * g_;

    #pragma unroll
    for (int it = 0; it < 8; it++) {
        const int o = it * 16;

        uint2 av = *(const uint2*)(fp + o);   // a0 = px o+2g_, a1 = px o+2g_+1
        unsigned a0 = av.x, a1 = av.y;

        // ---- layer 1: k8, f16-out (bias as C) ----
        unsigned d1[2][2];
        #pragma unroll
        for (int t = 0; t < 2; t++)
            mma8h(d1[t][0], d1[t][1], a0, a1, w1f[t], bias1h[t], bias1h[t]);

        unsigned A0 = max2z(d1[0][0]);
        unsigned A1 = max2z(d1[0][1]);
        unsigned A2 = max2z(d1[1][0]);
        unsigned A3 = max2z(d1[1][1]);

        // ---- layer 2: k16, f16-out (bias as C) ----
        unsigned d2[2][2];
        #pragma unroll
        for (int t = 0; t < 2; t++)
            mma16h(d2[t][0], d2[t][1], A0, A1, A2, A3,
                   w2f[t][0], w2f[t][1], bias2h[t], bias2h[t]);

        unsigned B0 = max2z(d2[0][0]);
        unsigned B1 = max2z(d2[0][1]);
        unsigned B2 = max2z(d2[1][0]);
        unsigned B3 = max2z(d2[1][1]);

        // ---- layer 3: k16, f32 accum; z broadcast to all lanes ----
        float d3[4];
        mma16f(d3[0], d3[1], d3[2], d3[3],
               B0, B1, B2, B3, w3f[0], w3f[1],
               b3v, b3v, b3v, b3v);

        // ---- sigmoid + adjacent-pair store ----
        if (c_ == 0) {
            float p0 = __fdividef(1.0f, 1.0f + __expf(-d3[0]));
            float p1 = __fdividef(1.0f, 1.0f + __expf(-d3[2]));
            *(float2*)(oprob + o + 2 * g_) = make_float2(p0, p1);
        }
    }

    // ---- iidd: pure index math, three coalesced STG.128 per row ----
    if (write_iidd) {
        const float fcid = (float)cid;
        const float frow = (float)row;
        const float fc0  = (float)(cx0 + 4 * lane);
        float4 vc = make_float4(fcid, fcid, fcid, fcid);
        float4 vr = make_float4(frow, frow, frow, frow);
        float4 vx = make_float4(fc0, fc0 + 1.0f, fc0 + 2.0f, fc0 + 3.0f);
        *(float4*)(out + PROB_ELEMS      + rowstart + 4 * lane) = vc;
        *(float4*)(out + 2L * PROB_ELEMS + rowstart + 4 * lane) = vr;
        *(float4*)(out + 3L * PROB_ELEMS + rowstart + 4 * lane) = vx;
    }
}

extern "C" void kernel_launch(void* const* d_in, const int* in_sizes, int n_in,
                              void* d_out, int out_size)
{
    const float* x     = (const float*)d_in[0];
    const float* sigma = (const float*)d_in[1];
    const float* cvec  = (const float*)d_in[2];
    const float* W1    = (const float*)d_in[3];
    const float* b1    = (const float*)d_in[4];
    const float* W2    = (const float*)d_in[5];
    const float* b2    = (const float*)d_in[6];
    const float* W3    = (const float*)d_in[7];
    const float* b3    = (const float*)d_in[8];
    const int*   cent  = (const int*)d_in[9];
    float* out = (float*)d_out;

    int write_iidd = (out_size >= 4 * PROB_ELEMS) ? 1 : 0;

    dim3 grid(BLOCKS_X, NC);
    instanseg_kernel<<<grid, THREADS>>>(x, sigma, cvec, W1, b1, W2, b2, W3, b3,
                                        cent, out, write_iidd);
}

// round 12
// speedup vs baseline: 3.9037x; 1.0378x over previous
#include <cuda_runtime.h>
#include <cuda_fp16.h>

#define IMG_H 1024
#define IMG_W 1024
#define IMG_HW (IMG_H * IMG_W)
#define WS 128
#define HALF 64
#define NE 6
#define NF 7
#define DH 16
#define NC 512
#define PX_PER_C (WS * WS)
#define PROB_ELEMS (NC * PX_PER_C)

#define THREADS 256          // 8 warps; each warp owns one window row
#define BLOCKS_X 16
#define PADW 136             // half2 words per pair-plane; conflict-free LDS.128

// pack two f32 -> f16x2 (rn); first arg lands in the LOW half
__device__ __forceinline__ unsigned cvt2h(float lo, float hi) {
    unsigned r; asm("cvt.rn.f16x2.f32 %0, %1, %2;" : "=r"(r) : "f"(hi), "f"(lo)); return r;
}
__device__ __forceinline__ unsigned max2z(unsigned v) {
    unsigned r; asm("max.f16x2 %0, %1, %2;" : "=r"(r) : "r"(v), "r"(0u)); return r;
}
// m16n8k8, all-f16
__device__ __forceinline__ void mma8h(unsigned& d0, unsigned& d1,
                                      unsigned a0, unsigned a1,
                                      unsigned b0,
                                      unsigned c0, unsigned c1) {
    asm volatile(
        "mma.sync.aligned.m16n8k8.row.col.f16.f16.f16.f16 "
        "{%0,%1}, {%2,%3}, {%4}, {%5,%6};"
        : "=r"(d0), "=r"(d1)
        : "r"(a0), "r"(a1), "r"(b0), "r"(c0), "r"(c1));
}
// m16n8k16, all-f16
__device__ __forceinline__ void mma16h(unsigned& d0, unsigned& d1,
                                       unsigned a0, unsigned a1, unsigned a2, unsigned a3,
                                       unsigned b0, unsigned b1,
                                       unsigned c0, unsigned c1) {
    asm volatile(
        "mma.sync.aligned.m16n8k16.row.col.f16.f16.f16.f16 "
        "{%0,%1}, {%2,%3,%4,%5}, {%6,%7}, {%8,%9};"
        : "=r"(d0), "=r"(d1)
        : "r"(a0), "r"(a1), "r"(a2), "r"(a3), "r"(b0), "r"(b1), "r"(c0), "r"(c1));
}
// m16n8k16, f16 in, f32 accumulate (final layer)
__device__ __forceinline__ void mma16f(float& d0, float& d1, float& d2, float& d3,
                                       unsigned a0, unsigned a1, unsigned a2, unsigned a3,
                                       unsigned b0, unsigned b1,
                                       float c0, float c1, float c2, float c3) {
    asm volatile(
        "mma.sync.aligned.m16n8k16.row.col.f32.f16.f16.f32 "
        "{%0,%1,%2,%3}, {%4,%5,%6,%7}, {%8,%9}, {%10,%11,%12,%13};"
        : "=f"(d0), "=f"(d1), "=f"(d2), "=f"(d3)
        : "r"(a0), "r"(a1), "r"(a2), "r"(a3), "r"(b0), "r"(b1),
          "f"(c0), "f"(c1), "f"(c2), "f"(c3));
}

__global__ __launch_bounds__(THREADS, 4)
void instanseg_kernel(const float* __restrict__ x,
                      const float* __restrict__ sigma,
                      const float* __restrict__ cvec,
                      const float* __restrict__ W1,
                      const float* __restrict__ b1,
                      const float* __restrict__ W2,
                      const float* __restrict__ b2,
                      const float* __restrict__ W3,
                      const float* __restrict__ b3,
                      const int*   __restrict__ cent,
                      float* __restrict__ out,
                      int write_iidd)
{
    __shared__ float b1cs[DH];                          // b1 - c[cid] @ W1[0:6]
    __shared__ __align__(16) unsigned h2buf[8][4 * PADW];  // [warp][pair][px] half2
    __shared__ int cy0s, cx0s;

    const int tid  = threadIdx.x;
    const int wid  = tid >> 5;
    const int lane = tid & 31;
    const int g_   = lane >> 2;
    const int c_   = lane & 3;
    const int cid  = blockIdx.y;

    if (tid < DH) {
        float acc = b1[tid];
        #pragma unroll
        for (int e = 0; e < NE; e++)
            acc -= cvec[cid * NE + e] * W1[e * DH + tid];
        b1cs[tid] = acc;
    }
    if (tid == 0) {
        int cy = cent[cid * 2 + 0];
        int cx = cent[cid * 2 + 1];
        cy = min(max(cy, HALF), IMG_H - HALF);
        cx = min(max(cx, HALF), IMG_W - HALF);
        cy0s = cy - HALF;
        cx0s = cx - HALF;
    }
    __syncthreads();

    const int cy0 = cy0s, cx0 = cx0s;

    // ---- weight fragments (packed f16x2) ----
    unsigned w1f[2], bias1h[2];
    #pragma unroll
    for (int t = 0; t < 2; t++) {
        int n = 8 * t + g_;
        float w0  = W1[(2 * c_) * DH + n];
        float w1v = (2 * c_ + 1 < NF) ? W1[(2 * c_ + 1) * DH + n] : 0.0f;
        w1f[t] = cvt2h(w0, w1v);
        bias1h[t] = cvt2h(b1cs[8 * t + 2 * c_], b1cs[8 * t + 2 * c_ + 1]);
    }
    unsigned w2f[2][2], bias2h[2];
    #pragma unroll
    for (int t = 0; t < 2; t++) {
        int n = 8 * t + g_;
        w2f[t][0] = cvt2h(W2[(2 * c_)     * DH + n], W2[(2 * c_ + 1) * DH + n]);
        w2f[t][1] = cvt2h(W2[(2 * c_ + 8) * DH + n], W2[(2 * c_ + 9) * DH + n]);
        bias2h[t] = cvt2h(b2[8 * t + 2 * c_], b2[8 * t + 2 * c_ + 1]);
    }
    unsigned w3f[2];
    w3f[0] = cvt2h(W3[2 * c_],     W3[2 * c_ + 1]);
    w3f[1] = cvt2h(W3[2 * c_ + 8], W3[2 * c_ + 9]);
    const float b3v = b3[0];

    // ---- stage this warp's row as pre-packed half2 feature pairs ----
    const int gy  = blockIdx.x * 8 + wid;
    const int row = cy0 + gy;
    unsigned* fw = h2buf[wid];
    {
        const long roff = (long)row * IMG_W + cx0;
        #pragma unroll
        for (int p = 0; p < 3; p++) {
            const float* f0 = x + (2 * p)     * IMG_HW + roff;
            const float* f1 = x + (2 * p + 1) * IMG_HW + roff;
            #pragma unroll
            for (int q = 0; q < 4; q++) {
                int col = q * 32 + lane;
                fw[p * PADW + col] = cvt2h(f0[col], f1[col]);
            }
        }
        const float* fs = sigma + roff;
        #pragma unroll
        for (int q = 0; q < 4; q++) {
            int col = q * 32 + lane;
            fw[3 * PADW + col] = cvt2h(fs[col], 0.0f);
        }
    }
    __syncwarp();

    const long rowstart = (long)cid * PX_PER_C + (long)gy * WS;
    float* oprob = out + rowstart;

    // two-tile pixel permutation within a 32-px group:
    //   tile A: row g_ <-> px o+4g_,   row g_+8 <-> px o+4g_+1
    //   tile B: row g_ <-> px o+4g_+2, row g_+8 <-> px o+4g_+3
    // -> this thread's four A-operands are ONE uint4 (LDS.128, conflict-free)
    const unsigned* fp = fw + c_ * PADW + 4 * g_;

    #pragma unroll
    for (int it = 0; it < 4; it++) {
        const int o = it * 32;
        uint4 av = *(const uint4*)(fp + o);

        // ================= tile A =================
        unsigned d1a[2][2];
        #pragma unroll
        for (int t = 0; t < 2; t++)
            mma8h(d1a[t][0], d1a[t][1], av.x, av.y, w1f[t], bias1h[t], bias1h[t]);
        unsigned A0 = max2z(d1a[0][0]), A1 = max2z(d1a[0][1]);
        unsigned A2 = max2z(d1a[1][0]), A3 = max2z(d1a[1][1]);

        unsigned d2a[2][2];
        #pragma unroll
        for (int t = 0; t < 2; t++)
            mma16h(d2a[t][0], d2a[t][1], A0, A1, A2, A3,
                   w2f[t][0], w2f[t][1], bias2h[t], bias2h[t]);
        unsigned Ba0 = max2z(d2a[0][0]), Ba1 = max2z(d2a[0][1]);
        unsigned Ba2 = max2z(d2a[1][0]), Ba3 = max2z(d2a[1][1]);

        float d3a[4];
        mma16f(d3a[0], d3a[1], d3a[2], d3a[3],
               Ba0, Ba1, Ba2, Ba3, w3f[0], w3f[1],
               b3v, b3v, b3v, b3v);

        // ================= tile B =================
        unsigned d1b[2][2];
        #pragma unroll
        for (int t = 0; t < 2; t++)
            mma8h(d1b[t][0], d1b[t][1], av.z, av.w, w1f[t], bias1h[t], bias1h[t]);
        unsigned C0 = max2z(d1b[0][0]), C1 = max2z(d1b[0][1]);
        unsigned C2 = max2z(d1b[1][0]), C3 = max2z(d1b[1][1]);

        unsigned d2b[2][2];
        #pragma unroll
        for (int t = 0; t < 2; t++)
            mma16h(d2b[t][0], d2b[t][1], C0, C1, C2, C3,
                   w2f[t][0], w2f[t][1], bias2h[t], bias2h[t]);
        unsigned Bb0 = max2z(d2b[0][0]), Bb1 = max2z(d2b[0][1]);
        unsigned Bb2 = max2z(d2b[1][0]), Bb3 = max2z(d2b[1][1]);

        float d3b[4];
        mma16f(d3b[0], d3b[1], d3b[2], d3b[3],
               Bb0, Bb1, Bb2, Bb3, w3f[0], w3f[1],
               b3v, b3v, b3v, b3v);

        // ---- sigmoid + 4-adjacent-pixel store (one STG.128 per 32 px) ----
        if (c_ == 0) {
            float p0 = __fdividef(1.0f, 1.0f + __expf(-d3a[0]));
            float p1 = __fdividef(1.0f, 1.0f + __expf(-d3a[2]));
            float p2 = __fdividef(1.0f, 1.0f + __expf(-d3b[0]));
            float p3 = __fdividef(1.0f, 1.0f + __expf(-d3b[2]));
            *(float4*)(oprob + o + 4 * g_) = make_float4(p0, p1, p2, p3);
        }
    }

    // ---- iidd: pure index math, three coalesced STG.128 per row ----
    if (write_iidd) {
        const float fcid = (float)cid;
        const float frow = (float)row;
        const float fc0  = (float)(cx0 + 4 * lane);
        float4 vc = make_float4(fcid, fcid, fcid, fcid);
        float4 vr = make_float4(frow, frow, frow, frow);
        float4 vx = make_float4(fc0, fc0 + 1.0f, fc0 + 2.0f, fc0 + 3.0f);
        *(float4*)(out + PROB_ELEMS      + rowstart + 4 * lane) = vc;
        *(float4*)(out + 2L * PROB_ELEMS + rowstart + 4 * lane) = vr;
        *(float4*)(out + 3L * PROB_ELEMS + rowstart + 4 * lane) = vx;
    }
}

extern "C" void kernel_launch(void* const* d_in, const int* in_sizes, int n_in,
                              void* d_out, int out_size)
{
    const float* x     = (const float*)d_in[0];
    const float* sigma = (const float*)d_in[1];
    const float* cvec  = (const float*)d_in[2];
    const float* W1    = (const float*)d_in[3];
    const float* b1    = (const float*)d_in[4];
    const float* W2    = (const float*)d_in[5];
    const float* b2    = (const float*)d_in[6];
    const float* W3    = (const float*)d_in[7];
    const float* b3    = (const float*)d_in[8];
    const int*   cent  = (const int*)d_in[9];
    float* out = (float*)d_out;

    int write_iidd = (out_size >= 4 * PROB_ELEMS) ? 1 : 0;

    dim3 grid(BLOCKS_X, NC);
    instanseg_kernel<<<grid, THREADS>>>(x, sigma, cvec, W1, b1, W2, b2, W3, b3,
                                        cent, out, write_iidd);
}

// round 13
// speedup vs baseline: 4.1921x; 1.0739x over previous
#include <cuda_runtime.h>
#include <cuda_fp16.h>

#define IMG_H 1024
#define IMG_W 1024
#define IMG_HW (IMG_H * IMG_W)
#define WS 128
#define HALF 64
#define NE 6
#define NF 7
#define DH 16
#define NC 512
#define PX_PER_C (WS * WS)
#define PROB_ELEMS (NC * PX_PER_C)

#define THREADS 256          // 8 warps; each warp owns one window row
#define BLOCKS_X 16
#define PADW 136             // half2 words per pair-plane; conflict-free LDS.128

// pack two f32 -> f16x2 (rn); first arg lands in the LOW half
__device__ __forceinline__ unsigned cvt2h(float lo, float hi) {
    unsigned r; asm("cvt.rn.f16x2.f32 %0, %1, %2;" : "=r"(r) : "f"(hi), "f"(lo)); return r;
}
__device__ __forceinline__ unsigned max2z(unsigned v) {
    unsigned r; asm("max.f16x2 %0, %1, %2;" : "=r"(r) : "r"(v), "r"(0u)); return r;
}
// m16n8k8, all-f16
__device__ __forceinline__ void mma8h(unsigned& d0, unsigned& d1,
                                      unsigned a0, unsigned a1,
                                      unsigned b0,
                                      unsigned c0, unsigned c1) {
    asm volatile(
        "mma.sync.aligned.m16n8k8.row.col.f16.f16.f16.f16 "
        "{%0,%1}, {%2,%3}, {%4}, {%5,%6};"
        : "=r"(d0), "=r"(d1)
        : "r"(a0), "r"(a1), "r"(b0), "r"(c0), "r"(c1));
}
// m16n8k16, all-f16
__device__ __forceinline__ void mma16h(unsigned& d0, unsigned& d1,
                                       unsigned a0, unsigned a1, unsigned a2, unsigned a3,
                                       unsigned b0, unsigned b1,
                                       unsigned c0, unsigned c1) {
    asm volatile(
        "mma.sync.aligned.m16n8k16.row.col.f16.f16.f16.f16 "
        "{%0,%1}, {%2,%3,%4,%5}, {%6,%7}, {%8,%9};"
        : "=r"(d0), "=r"(d1)
        : "r"(a0), "r"(a1), "r"(a2), "r"(a3), "r"(b0), "r"(b1), "r"(c0), "r"(c1));
}
// m16n8k16, f16 in, f32 accumulate (final layer)
__device__ __forceinline__ void mma16f(float& d0, float& d1, float& d2, float& d3,
                                       unsigned a0, unsigned a1, unsigned a2, unsigned a3,
                                       unsigned b0, unsigned b1,
                                       float c0, float c1, float c2, float c3) {
    asm volatile(
        "mma.sync.aligned.m16n8k16.row.col.f32.f16.f16.f32 "
        "{%0,%1,%2,%3}, {%4,%5,%6,%7}, {%8,%9}, {%10,%11,%12,%13};"
        : "=f"(d0), "=f"(d1), "=f"(d2), "=f"(d3)
        : "r"(a0), "r"(a1), "r"(a2), "r"(a3), "r"(b0), "r"(b1),
          "f"(c0), "f"(c1), "f"(c2), "f"(c3));
}

__global__ __launch_bounds__(THREADS, 4)
void instanseg_kernel(const float* __restrict__ x,
                      const float* __restrict__ sigma,
                      const float* __restrict__ cvec,
                      const float* __restrict__ W1,
                      const float* __restrict__ b1,
                      const float* __restrict__ W2,
                      const float* __restrict__ b2,
                      const float* __restrict__ W3,
                      const float* __restrict__ b3,
                      const int*   __restrict__ cent,
                      float* __restrict__ out,
                      int write_iidd)
{
    __shared__ float b1cs[DH];                             // b1 - c[cid] @ W1[0:6]
    __shared__ __align__(16) unsigned h2buf[8][4 * PADW];  // [warp][pair][px] half2
    __shared__ int cy0s, cx0s;

    const int tid  = threadIdx.x;
    const int wid  = tid >> 5;
    const int lane = tid & 31;
    const int g_   = lane >> 2;
    const int c_   = lane & 3;
    const int cid  = blockIdx.y;

    if (tid < DH) {
        float acc = b1[tid];
        #pragma unroll
        for (int e = 0; e < NE; e++)
            acc -= cvec[cid * NE + e] * W1[e * DH + tid];
        b1cs[tid] = acc;
    }
    if (tid == 0) {
        int cy = cent[cid * 2 + 0];
        int cx = cent[cid * 2 + 1];
        cy = min(max(cy, HALF), IMG_H - HALF);
        cx = min(max(cx, HALF), IMG_W - HALF);
        cy0s = cy - HALF;
        cx0s = cx - HALF;
    }
    __syncthreads();

    const int cy0 = cy0s, cx0 = cx0s;

    // ---- weight fragments (packed f16x2) ----
    unsigned w1f[2], bias1h[2];
    #pragma unroll
    for (int t = 0; t < 2; t++) {
        int n = 8 * t + g_;
        float w0  = W1[(2 * c_) * DH + n];
        float w1v = (2 * c_ + 1 < NF) ? W1[(2 * c_ + 1) * DH + n] : 0.0f;
        w1f[t] = cvt2h(w0, w1v);
        bias1h[t] = cvt2h(b1cs[8 * t + 2 * c_], b1cs[8 * t + 2 * c_ + 1]);
    }
    unsigned w2f[2][2], bias2h[2];
    #pragma unroll
    for (int t = 0; t < 2; t++) {
        int n = 8 * t + g_;
        w2f[t][0] = cvt2h(W2[(2 * c_)     * DH + n], W2[(2 * c_ + 1) * DH + n]);
        w2f[t][1] = cvt2h(W2[(2 * c_ + 8) * DH + n], W2[(2 * c_ + 9) * DH + n]);
        bias2h[t] = cvt2h(b2[8 * t + 2 * c_], b2[8 * t + 2 * c_ + 1]);
    }
    unsigned w3f[2];
    w3f[0] = cvt2h(W3[2 * c_],     W3[2 * c_ + 1]);
    w3f[1] = cvt2h(W3[2 * c_ + 8], W3[2 * c_ + 9]);
    const float b3v = b3[0];

    // ---- stage this warp's row as pre-packed half2 feature pairs ----
    const int gy  = blockIdx.x * 8 + wid;
    const int row = cy0 + gy;
    unsigned* fw = h2buf[wid];
    {
        const long roff = (long)row * IMG_W + cx0;
        #pragma unroll
        for (int p = 0; p < 3; p++) {
            const float* f0 = x + (2 * p)     * IMG_HW + roff;
            const float* f1 = x + (2 * p + 1) * IMG_HW + roff;
            #pragma unroll
            for (int q = 0; q < 4; q++) {
                int col = q * 32 + lane;
                fw[p * PADW + col] = cvt2h(f0[col], f1[col]);
            }
        }
        const float* fs = sigma + roff;
        #pragma unroll
        for (int q = 0; q < 4; q++) {
            int col = q * 32 + lane;
            fw[3 * PADW + col] = cvt2h(fs[col], 0.0f);
        }
    }
    __syncwarp();

    const long rowstart = (long)cid * PX_PER_C + (long)gy * WS;
    // all-lane store: lane's pixel within each 32-px group is 4g_ + c_
    float* oplane = out + rowstart + 4 * g_ + c_;

    // two-tile pixel permutation within each 32-px group:
    //   tile A: row g_ <-> px o+4g_,   row g_+8 <-> px o+4g_+1
    //   tile B: row g_ <-> px o+4g_+2, row g_+8 <-> px o+4g_+3
    const unsigned* fp = fw + c_ * PADW + 4 * g_;

    // ---- software pipeline: prefetch iter-0 operands ----
    uint4 av = *(const uint4*)(fp);

    #pragma unroll
    for (int it = 0; it < 4; it++) {
        const int o = it * 32;
        uint4 cur = av;
        if (it < 3) av = *(const uint4*)(fp + o + 32);   // prefetch next

        // ================= tile A =================
        unsigned d1a[2][2];
        #pragma unroll
        for (int t = 0; t < 2; t++)
            mma8h(d1a[t][0], d1a[t][1], cur.x, cur.y, w1f[t], bias1h[t], bias1h[t]);
        unsigned A0 = max2z(d1a[0][0]), A1 = max2z(d1a[0][1]);
        unsigned A2 = max2z(d1a[1][0]), A3 = max2z(d1a[1][1]);

        unsigned d2a[2][2];
        #pragma unroll
        for (int t = 0; t < 2; t++)
            mma16h(d2a[t][0], d2a[t][1], A0, A1, A2, A3,
                   w2f[t][0], w2f[t][1], bias2h[t], bias2h[t]);
        unsigned Ba0 = max2z(d2a[0][0]), Ba1 = max2z(d2a[0][1]);
        unsigned Ba2 = max2z(d2a[1][0]), Ba3 = max2z(d2a[1][1]);

        float d3a[4];
        mma16f(d3a[0], d3a[1], d3a[2], d3a[3],
               Ba0, Ba1, Ba2, Ba3, w3f[0], w3f[1],
               b3v, b3v, b3v, b3v);

        // ================= tile B =================
        unsigned d1b[2][2];
        #pragma unroll
        for (int t = 0; t < 2; t++)
            mma8h(d1b[t][0], d1b[t][1], cur.z, cur.w, w1f[t], bias1h[t], bias1h[t]);
        unsigned C0 = max2z(d1b[0][0]), C1 = max2z(d1b[0][1]);
        unsigned C2 = max2z(d1b[1][0]), C3 = max2z(d1b[1][1]);

        unsigned d2b[2][2];
        #pragma unroll
        for (int t = 0; t < 2; t++)
            mma16h(d2b[t][0], d2b[t][1], C0, C1, C2, C3,
                   w2f[t][0], w2f[t][1], bias2h[t], bias2h[t]);
        unsigned Bb0 = max2z(d2b[0][0]), Bb1 = max2z(d2b[0][1]);
        unsigned Bb2 = max2z(d2b[1][0]), Bb3 = max2z(d2b[1][1]);

        float d3b[4];
        mma16f(d3b[0], d3b[1], d3b[2], d3b[3],
               Bb0, Bb1, Bb2, Bb3, w3f[0], w3f[1],
               b3v, b3v, b3v, b3v);

        // ---- all-lane sigmoid + coalesced STG.32 ----
        // every lane holds all four z's (w3 cols identical -> broadcast);
        // lane selects its own pixel 4g_+c_ of this 32-px group.
        float z0 = (c_ & 2) ? d3b[0] : d3a[0];   // even sub-pixel (rows g_)
        float z1 = (c_ & 2) ? d3b[2] : d3a[2];   // odd sub-pixel (rows g_+8)
        float z  = (c_ & 1) ? z1 : z0;
        oplane[o] = __fdividef(1.0f, 1.0f + __expf(-z));
    }

    // ---- iidd: pure index math, three coalesced STG.128 per row ----
    if (write_iidd) {
        const float fcid = (float)cid;
        const float frow = (float)row;
        const float fc0  = (float)(cx0 + 4 * lane);
        float4 vc = make_float4(fcid, fcid, fcid, fcid);
        float4 vr = make_float4(frow, frow, frow, frow);
        float4 vx = make_float4(fc0, fc0 + 1.0f, fc0 + 2.0f, fc0 + 3.0f);
        *(float4*)(out + PROB_ELEMS      + rowstart + 4 * lane) = vc;
        *(float4*)(out + 2L * PROB_ELEMS + rowstart + 4 * lane) = vr;
        *(float4*)(out + 3L * PROB_ELEMS + rowstart + 4 * lane) = vx;
    }
}

extern "C" void kernel_launch(void* const* d_in, const int* in_sizes, int n_in,
                              void* d_out, int out_size)
{
    const float* x     = (const float*)d_in[0];
    const float* sigma = (const float*)d_in[1];
    const float* cvec  = (const float*)d_in[2];
    const float* W1    = (const float*)d_in[3];
    const float* b1    = (const float*)d_in[4];
    const float* W2    = (const float*)d_in[5];
    const float* b2    = (const float*)d_in[6];
    const float* W3    = (const float*)d_in[7];
    const float* b3    = (const float*)d_in[8];
    const int*   cent  = (const int*)d_in[9];
    float* out = (float*)d_out;

    int write_iidd = (out_size >= 4 * PROB_ELEMS) ? 1 : 0;

    dim3 grid(BLOCKS_X, NC);
    instanseg_kernel<<<grid, THREADS>>>(x, sigma, cvec, W1, b1, W2, b2, W3, b3,
                                        cent, out, write_iidd);
}